// round 14
// baseline (speedup 1.0000x reference)
#include <cuda_runtime.h>
#include <cuda_bf16.h>
#include <math.h>
#include <stdint.h>

#define BQ 16
#define NQ 2048
#define DQ 64
#define SQ 512
#define NSQ 32
#define SCQ 67
#define INCH 134
#define C0Q 128
#define C1Q 128
#define C2Q 256
#define KSQ (NSQ*SQ)
#define JQ (3+DQ+NSQ*DQ+NSQ*3)   // 2211
#define OFF_X 0
#define OFF_P 3
#define OFF_GP 67
#define OFF_GX 2115
#define XYZ_OUT (BQ*3*SQ)
#define NP_OUT  ((size_t)BQ*C2Q*SQ)
#define KP1 96
#define KPE 160

typedef unsigned short ush;

// ---------------- fp32 scratch ----------------
__device__ float g_h1t [(size_t)BQ*NQ*SCQ];
__device__ float g_h2  [(size_t)BQ*SQ*NQ];
__device__ float g_Cbig[(size_t)BQ*SQ*JQ];
__device__ float g_O0T [(size_t)BQ*KSQ*C0Q];
__device__ float g_O1T [(size_t)BQ*KSQ*C1Q];
__device__ float g_O2T [(size_t)BQ*KSQ*C2Q];
__device__ float g_norm[BQ*SQ];
__device__ int   g_amax[SQ];
__device__ int   g_idx[(size_t)BQ*NSQ*NQ];
__device__ double g_part[(size_t)2048*256*2];
__device__ float g_s1[SCQ], g_sh1[SCQ];
__device__ float g_s2[SQ],  g_sh2[SQ];
__device__ float g_sc0[C0Q], g_sf0[C0Q];
__device__ float g_sc1[C1Q], g_sf1[C1Q];
__device__ float g_sc2[C2Q], g_sf2[C2Q];
__device__ float g_acc[BQ];
__device__ int   g_flags[NQ];

// ---------------- bf16 hi/lo operand arrays ----------------
__device__ ush g_aggc_h[(size_t)BQ*NQ*KP1],  g_aggc_l[(size_t)BQ*NQ*KP1];
__device__ ush g_w1c_h[SCQ*KP1],             g_w1c_l[SCQ*KP1];
__device__ ush g_h1c_h[(size_t)BQ*NQ*KP1],   g_h1c_l[(size_t)BQ*NQ*KP1];
__device__ ush g_w2c_h[SQ*KP1],              g_w2c_l[SQ*KP1];
__device__ ush g_Sc_h[(size_t)BQ*SQ*NQ],     g_Sc_l[(size_t)BQ*SQ*NQ];
__device__ ush g_BmTc_h[(size_t)BQ*JQ*NQ],   g_BmTc_l[(size_t)BQ*JQ*NQ];
__device__ ush g_c0wc_h[C0Q*KPE],            g_c0wc_l[C0Q*KPE];
__device__ ush g_c1wc_h[C1Q*C0Q],            g_c1wc_l[C1Q*C0Q];
__device__ ush g_c2wc_h[C2Q*C1Q],            g_c2wc_l[C2Q*C1Q];

// ---------------- helpers ----------------
__device__ __forceinline__ uint32_t smem_u32(const void* p) {
    uint32_t a;
    asm("{ .reg .u64 t; cvta.to.shared.u64 t, %1; cvt.u32.u64 %0, t; }" : "=r"(a) : "l"(p));
    return a;
}
__device__ __forceinline__ void ldm4(uint32_t* r, uint32_t addr) {
    asm volatile("ldmatrix.sync.aligned.m8n8.x4.shared.b16 {%0,%1,%2,%3}, [%4];"
        : "=r"(r[0]), "=r"(r[1]), "=r"(r[2]), "=r"(r[3]) : "r"(addr));
}
__device__ __forceinline__ void mma16816(float* c, const uint32_t* a, const uint32_t* b) {
    asm volatile("mma.sync.aligned.m16n8k16.row.col.f32.bf16.bf16.f32 "
        "{%0,%1,%2,%3}, {%4,%5,%6,%7}, {%8,%9}, {%0,%1,%2,%3};"
        : "+f"(c[0]), "+f"(c[1]), "+f"(c[2]), "+f"(c[3])
        : "r"(a[0]), "r"(a[1]), "r"(a[2]), "r"(a[3]), "r"(b[0]), "r"(b[1]));
}
__device__ __forceinline__ uint32_t split_pack(float v0, float v1, uint32_t* lo) {
    __nv_bfloat16 h0 = __float2bfloat16(v0), h1 = __float2bfloat16(v1);
    __nv_bfloat16 l0 = __float2bfloat16(v0 - __bfloat162float(h0));
    __nv_bfloat16 l1 = __float2bfloat16(v1 - __bfloat162float(h1));
    *lo = ((uint32_t)__bfloat16_as_ushort(l1) << 16) | __bfloat16_as_ushort(l0);
    return ((uint32_t)__bfloat16_as_ushort(h1) << 16) | __bfloat16_as_ushort(h0);
}
__device__ __forceinline__ void split_write(float v, ush* ph, ush* pl) {
    __nv_bfloat16 h = __float2bfloat16(v);
    __nv_bfloat16 l = __float2bfloat16(v - __bfloat162float(h));
    *ph = __bfloat16_as_ushort(h);
    *pl = __bfloat16_as_ushort(l);
}
__device__ __forceinline__ float edge_val(const float* __restrict__ Cr, int k, int c) {
    if (c < 64) return Cr[OFF_P + c];
    if (c < 128) { int d = c - 64; return Cr[OFF_GP + k*DQ + d] - Cr[OFF_P + d]; }
    if (c < 131) return Cr[OFF_X + (c - 128)];
    if (c < INCH) { int c3 = c - 131; return Cr[OFF_GX + k*3 + c3] - Cr[OFF_X + c3]; }
    return 0.f;
}

// ---------------- pipelined HMMA GEMM (2-stage) with fused loaders/epilogues ----
// aMode: 0 = A pre-split bf16 via cp.async; 1 = A fp32 (affine+leaky) staged through
// smem via cp.async then converted; 2 = A edge features gathered from Cbig.
#define KC 32
#define RSH 40
#define TILEH (128*RSH)
#define STAGEH (4*TILEH)
#define SMEM_BYTES (2*STAGEH*2)            // 81920 B (aMode 0/2)
#define STG_BYTES (128*KC*4)               // 16384 B fp32 staging per stage
#define SMEM_A1_BYTES (SMEM_BYTES + 2*STG_BYTES)  // 114688 B (aMode 1)
__global__ void __launch_bounds__(256, 2) mma_gemm(
    const ush* __restrict__ Ah, const ush* __restrict__ Al,
    const ush* __restrict__ Bh, const ush* __restrict__ Bl,
    float* __restrict__ C, int M, int N, int Kp,
    size_t sA, size_t sB, size_t sC,
    const float* __restrict__ biasRow, const float* __restrict__ biasCol,
    int statMode, double* __restrict__ statOut, int statC, int triSkip, int cosMode,
    int aMode, const float* __restrict__ Afp, size_t sAfp,
    const float* __restrict__ scA, const float* __restrict__ shA)
{
    if (triSkip && blockIdx.x < blockIdx.y) return;
    extern __shared__ ush sm[];
    const int tid = threadIdx.x;
    const int w = tid >> 5, lane = tid & 31;
    const int wm = w & 1, wn = w >> 1;
    const int m0 = blockIdx.y * 128, n0 = blockIdx.x * 128, b = blockIdx.z;
    const ush* srcs[4] = { Ah + (size_t)b*sA, Al + (size_t)b*sA,
                           Bh + (size_t)b*sB, Bl + (size_t)b*sB };
    const float* Afpb = Afp ? (Afp + (size_t)b * sAfp) : (const float*)0;
    const uint32_t smb = smem_u32(sm);

    float acc[4][4][4];
    #pragma unroll
    for (int i = 0; i < 4; i++)
        #pragma unroll
        for (int j = 0; j < 4; j++)
            #pragma unroll
            for (int q = 0; q < 4; q++) acc[i][j][q] = 0.f;

    const int T = Kp / KC;

    #define LOAD_STAGE(t, st) do { \
        int k0 = (t) * KC; \
        if (aMode == 0) { \
            _Pragma("unroll") \
            for (int arr = 0; arr < 2; arr++) { \
                const ush* S = srcs[arr]; \
                uint32_t dbase = smb + (uint32_t)(((st)*STAGEH + arr*TILEH) * 2); \
                _Pragma("unroll") \
                for (int i = 0; i < 2; i++) { \
                    int e = tid + i * 256; \
                    int r = e >> 2, c16 = e & 3; \
                    uint32_t daddr = dbase + (uint32_t)((r * RSH + c16 * 8) * 2); \
                    int rg = m0 + r; \
                    int rc = rg < M ? rg : (M - 1); \
                    const ush* sp = S + (size_t)rc * Kp + k0 + c16 * 8; \
                    int sz = (rg < M) ? 16 : 0; \
                    asm volatile("cp.async.cg.shared.global [%0], [%1], 16, %2;" \
                                 :: "r"(daddr), "l"(sp), "r"(sz)); \
                } \
            } \
        } else if (aMode == 1) { \
            /* stage fp32 A-chunk through smem (contiguous 128B rows) */ \
            _Pragma("unroll") \
            for (int i = 0; i < 4; i++) { \
                int e = tid + i * 256; \
                int r = e >> 3, c4 = e & 7; \
                uint32_t daddr = smb + (uint32_t)SMEM_BYTES + (uint32_t)((st)*STG_BYTES) \
                                 + (uint32_t)(r * 128 + c4 * 16); \
                int rg = m0 + r; \
                int rc = rg < M ? rg : (M - 1); \
                const float* sp = Afpb + (size_t)rc * Kp + k0 + c4 * 4; \
                int sz = (rg < M) ? 16 : 0; \
                asm volatile("cp.async.cg.shared.global [%0], [%1], 16, %2;" \
                             :: "r"(daddr), "l"(sp), "r"(sz)); \
            } \
        } else { \
            _Pragma("unroll") \
            for (int i = 0; i < 8; i++) { \
                int e = tid + i * 256; \
                int r = e >> 4, cw = e & 15; \
                int rg = m0 + r, kk = k0 + cw * 2; \
                int kgrp = rg >> 9, sloc = rg & 511; \
                const float* Cr = Afpb + (size_t)sloc * JQ; \
                float v0 = edge_val(Cr, kgrp, kk); \
                float v1 = edge_val(Cr, kgrp, kk + 1); \
                uint32_t lw, hw = split_pack(v0, v1, &lw); \
                int idx = (st)*STAGEH + r * RSH + cw * 2; \
                *(uint32_t*)&sm[idx] = hw; \
                *(uint32_t*)&sm[idx + TILEH] = lw; \
            } \
        } \
        _Pragma("unroll") \
        for (int arr = 2; arr < 4; arr++) { \
            const ush* S = srcs[arr]; \
            uint32_t dbase = smb + (uint32_t)(((st)*STAGEH + arr*TILEH) * 2); \
            _Pragma("unroll") \
            for (int i = 0; i < 2; i++) { \
                int e = tid + i * 256; \
                int r = e >> 2, c16 = e & 3; \
                uint32_t daddr = dbase + (uint32_t)((r * RSH + c16 * 8) * 2); \
                int rg = n0 + r; \
                int rc = rg < N ? rg : (N - 1); \
                const ush* sp = S + (size_t)rc * Kp + k0 + c16 * 8; \
                int sz = (rg < N) ? 16 : 0; \
                asm volatile("cp.async.cg.shared.global [%0], [%1], 16, %2;" \
                             :: "r"(daddr), "l"(sp), "r"(sz)); \
            } \
        } \
        asm volatile("cp.async.commit_group;" ::: "memory"); \
    } while (0)

    // convert staged fp32 chunk (stage st, K-chunk tcur) to bf16 hi/lo tiles
    #define CONVERT_A1(st, tcur) do { \
        const float* stg = (const float*)((const char*)sm + SMEM_BYTES + (st)*STG_BYTES); \
        int k0c = (tcur) * KC; \
        _Pragma("unroll") \
        for (int i = 0; i < 8; i++) { \
            int e = tid + i * 256; \
            int r = e >> 4, cw = e & 15; \
            int rg = m0 + r, kk = k0c + cw * 2; \
            float v0 = 0.f, v1 = 0.f; \
            if (rg < M) { \
                v0 = stg[r * 32 + cw * 2]; \
                v1 = stg[r * 32 + cw * 2 + 1]; \
                v0 = scA[kk] * v0 + shA[kk];       if (v0 < 0.f) v0 *= 0.2f; \
                v1 = scA[kk+1] * v1 + shA[kk+1];   if (v1 < 0.f) v1 *= 0.2f; \
            } \
            uint32_t lw, hw = split_pack(v0, v1, &lw); \
            int idx = (st)*STAGEH + r * RSH + cw * 2; \
            *(uint32_t*)&sm[idx] = hw; \
            *(uint32_t*)&sm[idx + TILEH] = lw; \
        } \
    } while (0)

    LOAD_STAGE(0, 0);
    for (int t = 0; t < T; t++) {
        const int st = t & 1;
        if (t + 1 < T) {
            LOAD_STAGE(t + 1, st ^ 1);
            asm volatile("cp.async.wait_group 1;" ::: "memory");
        } else {
            asm volatile("cp.async.wait_group 0;" ::: "memory");
        }
        __syncthreads();
        if (aMode == 1) {
            CONVERT_A1(st, t);
            __syncthreads();
        }
        const uint32_t uAh = smb + (uint32_t)((st*STAGEH + 0*TILEH) * 2);
        const uint32_t uAl = smb + (uint32_t)((st*STAGEH + 1*TILEH) * 2);
        const uint32_t uBh = smb + (uint32_t)((st*STAGEH + 2*TILEH) * 2);
        const uint32_t uBl = smb + (uint32_t)((st*STAGEH + 3*TILEH) * 2);
        #pragma unroll
        for (int k16 = 0; k16 < 32; k16 += 16) {
            const int arow = wm * 64 + (lane & 15);
            const int akk = k16 + ((lane >> 4) << 3);
            uint32_t bh[4][2], bl[4][2];
            {
                int q = lane >> 3;
                int brow0 = wn * 32 + ((q >> 1) << 3) + (lane & 7);
                int bkk = k16 + ((q & 1) << 3);
                #pragma unroll
                for (int p = 0; p < 2; p++) {
                    uint32_t byteoff = (uint32_t)(((brow0 + p * 16) * RSH + bkk) << 1);
                    uint32_t tmp[4];
                    ldm4(tmp, uBh + byteoff);
                    bh[2*p][0] = tmp[0]; bh[2*p][1] = tmp[1];
                    bh[2*p+1][0] = tmp[2]; bh[2*p+1][1] = tmp[3];
                    ldm4(tmp, uBl + byteoff);
                    bl[2*p][0] = tmp[0]; bl[2*p][1] = tmp[1];
                    bl[2*p+1][0] = tmp[2]; bl[2*p+1][1] = tmp[3];
                }
            }
            {
                uint32_t ah[4][4];
                #pragma unroll
                for (int mf = 0; mf < 4; mf++) {
                    uint32_t byteoff = (uint32_t)(((arow + mf * 16) * RSH + akk) << 1);
                    ldm4(ah[mf], uAh + byteoff);
                }
                #pragma unroll
                for (int mf = 0; mf < 4; mf++)
                    #pragma unroll
                    for (int nf = 0; nf < 4; nf++)
                        mma16816(acc[mf][nf], ah[mf], bh[nf]);
                #pragma unroll
                for (int mf = 0; mf < 4; mf++)
                    #pragma unroll
                    for (int nf = 0; nf < 4; nf++)
                        mma16816(acc[mf][nf], ah[mf], bl[nf]);
            }
            {
                uint32_t al[4][4];
                #pragma unroll
                for (int mf = 0; mf < 4; mf++) {
                    uint32_t byteoff = (uint32_t)(((arow + mf * 16) * RSH + akk) << 1);
                    ldm4(al[mf], uAl + byteoff);
                }
                #pragma unroll
                for (int mf = 0; mf < 4; mf++)
                    #pragma unroll
                    for (int nf = 0; nf < 4; nf++)
                        mma16816(acc[mf][nf], al[mf], bh[nf]);
            }
        }
        __syncthreads();
    }

    if (cosMode) {
        const float* nb = g_norm + b * SQ;
        float part = 0.f;
        #pragma unroll
        for (int mf = 0; mf < 4; mf++) {
            int r = m0 + wm * 64 + mf * 16 + (lane >> 2);
            float nr0 = nb[r], nr1 = nb[r + 8];
            #pragma unroll
            for (int nf = 0; nf < 4; nf++) {
                #pragma unroll
                for (int u = 0; u < 2; u++) {
                    int col = n0 + wn * 32 + nf * 8 + ((lane & 3) << 1) + u;
                    float ncv = nb[col];
                    if (col > r) {
                        float cm = acc[mf][nf][u] / (nr0 * ncv + 1e-10f);
                        part += 2.f * cm * cm;
                    }
                    if (col > r + 8) {
                        float cm = acc[mf][nf][u + 2] / (nr1 * ncv + 1e-10f);
                        part += 2.f * cm * cm;
                    }
                }
            }
        }
        float* red = (float*)sm;
        red[tid] = part; __syncthreads();
        for (int off = 128; off > 0; off >>= 1) {
            if (tid < off) red[tid] += red[tid + off];
            __syncthreads();
        }
        if (tid == 0) atomicAdd(&g_acc[b], red[0]);
        return;
    }

    float cs[8], cq[8];
    #pragma unroll
    for (int i = 0; i < 8; i++) { cs[i] = 0.f; cq[i] = 0.f; }
    float* Cb = C + (size_t)b * sC;
    #pragma unroll
    for (int mf = 0; mf < 4; mf++) {
        int r = m0 + wm * 64 + mf * 16 + (lane >> 2);
        float br0 = biasRow ? biasRow[r] : 0.f;
        float br1 = biasRow ? biasRow[r + 8] : 0.f;
        #pragma unroll
        for (int nf = 0; nf < 4; nf++) {
            int c = n0 + wn * 32 + nf * 8 + ((lane & 3) << 1);
            #pragma unroll
            for (int u = 0; u < 2; u++) {
                int col = c + u;
                float bc = (biasCol && col < N) ? biasCol[col] : 0.f;
                float v0 = acc[mf][nf][u]     + br0 + bc;
                float v1 = acc[mf][nf][u + 2] + br1 + bc;
                if (col < N) {
                    Cb[(size_t)r * N + col]       = v0;
                    Cb[(size_t)(r + 8) * N + col] = v1;
                }
                if (statMode == 1) {
                    cs[nf*2+u] += v0 + v1;
                    cq[nf*2+u] += v0*v0 + v1*v1;
                } else if (statMode == 2) {
                    cs[mf*2]   += v0; cq[mf*2]   += v0*v0;
                    cs[mf*2+1] += v1; cq[mf*2+1] += v1*v1;
                }
            }
        }
    }
    if (statMode == 0) return;
    float* ssum = (float*)sm;
    float* ssq  = ssum + 2048;
    if (statMode == 1) {
        int g = wm * 8 + (lane >> 2);
        #pragma unroll
        for (int nf = 0; nf < 4; nf++)
            #pragma unroll
            for (int u = 0; u < 2; u++) {
                int colL = wn * 32 + nf * 8 + ((lane & 3) << 1) + u;
                ssum[colL * 16 + g] = cs[nf*2+u];
                ssq [colL * 16 + g] = cq[nf*2+u];
            }
        __syncthreads();
        if (tid < 128) {
            double s = 0.0, q = 0.0;
            #pragma unroll
            for (int g2 = 0; g2 < 16; g2++) { s += ssum[tid*16+g2]; q += ssq[tid*16+g2]; }
            int gcol = n0 + tid;
            if (gcol < N) {
                int chunk = blockIdx.z * gridDim.y + blockIdx.y;
                statOut[((size_t)chunk * statC + gcol) * 2]     = s;
                statOut[((size_t)chunk * statC + gcol) * 2 + 1] = q;
            }
        }
    } else {
        int h = wn * 4 + (lane & 3);
        #pragma unroll
        for (int mf = 0; mf < 4; mf++)
            #pragma unroll
            for (int hf = 0; hf < 2; hf++) {
                int rowL = wm * 64 + mf * 16 + (lane >> 2) + hf * 8;
                ssum[rowL * 16 + h] = cs[mf*2+hf];
                ssq [rowL * 16 + h] = cq[mf*2+hf];
            }
        __syncthreads();
        if (tid < 128) {
            double s = 0.0, q = 0.0;
            #pragma unroll
            for (int h2 = 0; h2 < 16; h2++) { s += ssum[tid*16+h2]; q += ssq[tid*16+h2]; }
            int grow = m0 + tid;
            int chunk = blockIdx.z * gridDim.x + blockIdx.x;
            statOut[((size_t)chunk * statC + grow) * 2]     = s;
            statOut[((size_t)chunk * statC + grow) * 2 + 1] = q;
        }
    }
}

// ---------------- elementwise / setup kernels ----------------
__global__ void sa_init() {
    int i = blockIdx.x * 256 + threadIdx.x;
    if (i < NQ) g_flags[i] = 0;
    if (i < BQ) g_acc[i] = 0.f;
}

__global__ void cv_split(const float* __restrict__ src, ush* __restrict__ dh, ush* __restrict__ dl,
                         long long totalPairs, int Ksrc, int Kp,
                         const float* __restrict__ sc, const float* __restrict__ sh, int leaky)
{
    long long i = (long long)blockIdx.x * 256 + threadIdx.x;
    if (i >= totalPairs) return;
    long long e = i * 2;
    int c = (int)(e % Kp);
    long long r = e / Kp;
    float v0 = 0.f, v1 = 0.f;
    if (c < Ksrc) {
        v0 = src[r * Ksrc + c];
        if (sc) { v0 = sc[c]*v0 + sh[c]; if (leaky && v0 < 0.f) v0 *= 0.2f; }
    }
    if (c + 1 < Ksrc) {
        v1 = src[r * Ksrc + c + 1];
        if (sc) { v1 = sc[c+1]*v1 + sh[c+1]; if (leaky && v1 < 0.f) v1 *= 0.2f; }
    }
    uint32_t lw, hw = split_pack(v0, v1, &lw);
    ((uint32_t*)dh)[i] = hw;
    ((uint32_t*)dl)[i] = lw;
}

__global__ void cv_agg(const float* __restrict__ points, const float* __restrict__ xyz) {
    long long i = (long long)blockIdx.x * 256 + threadIdx.x;
    if (i >= (long long)BQ*NQ*KP1/2) return;
    long long e = i * 2;
    int c = (int)(e % KP1); long long r = e / KP1;
    int n = (int)(r % NQ); int b = (int)(r / NQ);
    float v0 = 0.f, v1 = 0.f;
    if (c < DQ) v0 = points[((size_t)b*DQ + c)*NQ + n];
    else if (c < SCQ) v0 = xyz[((size_t)b*3 + (c-DQ))*NQ + n];
    int c1 = c + 1;
    if (c1 < DQ) v1 = points[((size_t)b*DQ + c1)*NQ + n];
    else if (c1 < SCQ) v1 = xyz[((size_t)b*3 + (c1-DQ))*NQ + n];
    uint32_t lw, hw = split_pack(v0, v1, &lw);
    ((uint32_t*)g_aggc_h)[i] = hw;
    ((uint32_t*)g_aggc_l)[i] = lw;
}

__global__ void sa_ball(const float* __restrict__ xyz) {
    int w = (blockIdx.x * blockDim.x + threadIdx.x) >> 5;
    int lane = threadIdx.x & 31;
    if (w >= BQ * NQ) return;
    int b = w / NQ, n = w % NQ;
    const float* X = xyz + (size_t)b * 3 * NQ;
    float px = X[n], py = X[NQ+n], pz = X[2*NQ+n];
    float pn = px*px + py*py + pz*pz;
    const float RR = (float)(0.2 * 0.2);
    int* out = g_idx + (size_t)b * NSQ * NQ + n;
    int cnt = 0;
    for (int j0 = 0; j0 < NQ && cnt < NSQ; j0 += 32) {
        int j = j0 + lane;
        float qx = X[j], qy = X[NQ+j], qz = X[2*NQ+j];
        float sq = (pn + qx*qx+qy*qy+qz*qz) - 2.0f*(px*qx+py*qy+pz*qz);
        bool in = !(sq > RR);
        unsigned m = __ballot_sync(0xffffffffu, in);
        int pos = cnt + __popc(m & ((1u << lane) - 1u));
        if (in && pos < NSQ) out[(size_t)pos * NQ] = j;
        cnt += __popc(m);
    }
    __syncwarp();
    if (lane == 0) {
        int first = out[0];
        for (int t = cnt; t < NSQ; t++) out[(size_t)t * NQ] = first;
    }
}

__global__ void sa_bmt_c(const float* __restrict__ points, const float* __restrict__ xyz) {
    int n = (blockIdx.x * 256 + threadIdx.x) * 2;
    int j = blockIdx.y, b = blockIdx.z;
    float v0, v1;
    if (j < OFF_P) {
        const float* p = xyz + ((size_t)b*3 + j)*NQ;
        v0 = p[n]; v1 = p[n+1];
    } else if (j < OFF_GP) {
        const float* p = points + ((size_t)b*DQ + (j-OFF_P))*NQ;
        v0 = p[n]; v1 = p[n+1];
    } else if (j < OFF_GX) {
        int t = j - OFF_GP, k = t >> 6, d = t & 63;
        const int* ip = g_idx + ((size_t)b*NSQ + k)*NQ;
        const float* p = points + ((size_t)b*DQ + d)*NQ;
        v0 = p[ip[n]]; v1 = p[ip[n+1]];
    } else {
        int t = j - OFF_GX, k = t / 3, c = t % 3;
        const int* ip = g_idx + ((size_t)b*NSQ + k)*NQ;
        const float* p = xyz + ((size_t)b*3 + c)*NQ;
        v0 = p[ip[n]]; v1 = p[ip[n+1]];
    }
    size_t o = (((size_t)b*JQ + j)*NQ + n) >> 1;
    uint32_t lw, hw = split_pack(v0, v1, &lw);
    ((uint32_t*)g_BmTc_h)[o] = hw;
    ((uint32_t*)g_BmTc_l)[o] = lw;
}

__global__ void sa_cs_fin(int C, int nChunks, int count,
                          const float* __restrict__ gamma, const float* __restrict__ beta,
                          float* __restrict__ sc, float* __restrict__ sf) {
    int c = blockIdx.x, tid = threadIdx.x;
    double s = 0.0, s2 = 0.0;
    for (int i = tid; i < nChunks; i += 256) {
        s  += g_part[((size_t)i * C + c) * 2];
        s2 += g_part[((size_t)i * C + c) * 2 + 1];
    }
    __shared__ double sa[256], sb2[256];
    sa[tid] = s; sb2[tid] = s2; __syncthreads();
    for (int o = 128; o > 0; o >>= 1) {
        if (tid < o) { sa[tid] += sa[tid+o]; sb2[tid] += sb2[tid+o]; }
        __syncthreads();
    }
    if (tid == 0) {
        double n = (double)count, m = sa[0] / n;
        double var = sb2[0] / n - m * m; if (var < 0.0) var = 0.0;
        float scale = gamma[c] * rsqrtf((float)var + 1e-5f);
        sc[c] = scale; sf[c] = beta[c] - (float)m * scale;
    }
}

__global__ void sa_softmax(float* __restrict__ H) {
    int s = blockIdx.x, b = blockIdx.y, tid = threadIdx.x;
    float* row = H + ((size_t)b * SQ + s) * NQ;
    __shared__ float buf[NQ];
    __shared__ float red[256], rv[256];
    __shared__ int ri[256];
    float a = g_s2[s], sh = g_sh2[s];
    float lmax = -3.4e38f;
    for (int i = tid; i < NQ; i += 256) { float y = a*row[i]+sh; buf[i] = y; lmax = fmaxf(lmax, y); }
    red[tid] = lmax; __syncthreads();
    for (int o = 128; o > 0; o >>= 1) { if (tid < o) red[tid] = fmaxf(red[tid], red[tid+o]); __syncthreads(); }
    float gmax = red[0]; __syncthreads();
    float lsum = 0.f;
    for (int i = tid; i < NQ; i += 256) { float e = __expf(buf[i]-gmax); buf[i] = e; lsum += e; }
    red[tid] = lsum; __syncthreads();
    for (int o = 128; o > 0; o >>= 1) { if (tid < o) red[tid] += red[tid+o]; __syncthreads(); }
    float inv = 1.f / red[0]; __syncthreads();
    float lss = 0.f, bm = -1.f; int bi = 0;
    size_t rowoff = ((size_t)b * SQ + s) * NQ;
    for (int i = tid; i < NQ; i += 256) {
        float v = buf[i] * inv; lss += v*v;
        split_write(v, g_Sc_h + rowoff + i, g_Sc_l + rowoff + i);
        if (v > bm) { bm = v; bi = i; }
    }
    red[tid] = lss; rv[tid] = bm; ri[tid] = bi; __syncthreads();
    for (int o = 128; o > 0; o >>= 1) {
        if (tid < o) {
            red[tid] += red[tid+o];
            if (rv[tid+o] > rv[tid] || (rv[tid+o] == rv[tid] && ri[tid+o] < ri[tid])) { rv[tid] = rv[tid+o]; ri[tid] = ri[tid+o]; }
        }
        __syncthreads();
    }
    if (tid == 0) {
        g_norm[b*SQ+s] = sqrtf(red[0]);
        if (b == 0) g_amax[s] = ri[0];
    }
}

__global__ void sa_flags() { int s = blockIdx.x*256 + threadIdx.x; if (s < SQ) g_flags[g_amax[s]] = 1; }

__global__ void sa_newxyz(float* __restrict__ out) {
    int i = blockIdx.x * 256 + threadIdx.x;
    if (i >= BQ*3*SQ) return;
    int s = i % SQ, c = (i/SQ) % 3, b = i/(3*SQ);
    out[i] = g_Cbig[((size_t)b*SQ + s)*JQ + OFF_X + c];
}

__global__ void sa_max(float* __restrict__ out) {
    int s = blockIdx.x, b = blockIdx.y, o = threadIdx.x;
    float sc = g_sc2[o], sf = g_sf2[o];
    float m = -3.4e38f;
    const float* base = g_O2T + ((size_t)b*KSQ + s)*C2Q + o;
    #pragma unroll
    for (int k = 0; k < NSQ; k++) {
        float y = sc * base[(size_t)k*SQ*C2Q] + sf;
        y = (y >= 0.f) ? y : 0.2f * y;
        m = fmaxf(m, y);
    }
    out[XYZ_OUT + ((size_t)b*C2Q + o)*SQ + s] = m;
}

__global__ void sa_scalars(float* __restrict__ out) {
    __shared__ float sfr[256]; __shared__ int sir[256];
    int tid = threadIdx.x;
    int cnt = 0;
    for (int i = tid; i < NQ; i += 256) cnt += g_flags[i];
    float l = (tid < BQ) ? sqrtf(g_acc[tid]) : 0.f;
    sfr[tid] = l; sir[tid] = cnt; __syncthreads();
    for (int o = 128; o > 0; o >>= 1) {
        if (tid < o) { sfr[tid] += sfr[tid+o]; sir[tid] += sir[tid+o]; }
        __syncthreads();
    }
    if (tid == 0) {
        out[XYZ_OUT + NP_OUT] = sfr[0] / (float)BQ;
        out[XYZ_OUT + NP_OUT + 1] = (float)sir[0];
    }
}

// ---------------- launch ----------------
static inline float*  symf(const void* sym) { void* p = nullptr; cudaGetSymbolAddress(&p, sym); return (float*)p; }
static inline ush*    symu(const void* sym) { void* p = nullptr; cudaGetSymbolAddress(&p, sym); return (ush*)p; }
static inline double* symd(const void* sym) { void* p = nullptr; cudaGetSymbolAddress(&p, sym); return (double*)p; }

extern "C" void kernel_launch(void* const* d_in, const int* in_sizes, int n_in,
                              void* d_out, int out_size)
{
    const float* xyz   = (const float*)d_in[0];
    const float* points= (const float*)d_in[1];
    const float* w1_w = (const float*)d_in[2];
    const float* w1_b = (const float*)d_in[3];
    const float* bn1g = (const float*)d_in[4];
    const float* bn1b = (const float*)d_in[5];
    const float* w2_w = (const float*)d_in[6];
    const float* w2_b = (const float*)d_in[7];
    const float* bn2g = (const float*)d_in[8];
    const float* bn2b = (const float*)d_in[9];
    const float* c0w = (const float*)d_in[10];
    const float* c0b = (const float*)d_in[11];
    const float* g0  = (const float*)d_in[12];
    const float* b0  = (const float*)d_in[13];
    const float* c1w = (const float*)d_in[14];
    const float* c1b = (const float*)d_in[15];
    const float* g1  = (const float*)d_in[16];
    const float* b1  = (const float*)d_in[17];
    const float* c2w = (const float*)d_in[18];
    const float* c2b = (const float*)d_in[19];
    const float* g2  = (const float*)d_in[20];
    const float* b2  = (const float*)d_in[21];
    float* out = (float*)d_out;

    static bool inited = false;
    static cudaStream_t s1;
    static cudaEvent_t eA, eB, eS, eG;
    if (!inited) {
        cudaFuncSetAttribute(mma_gemm, cudaFuncAttributeMaxDynamicSharedMemorySize, SMEM_A1_BYTES);
        cudaStreamCreateWithFlags(&s1, cudaStreamNonBlocking);
        cudaEventCreateWithFlags(&eA, cudaEventDisableTiming);
        cudaEventCreateWithFlags(&eB, cudaEventDisableTiming);
        cudaEventCreateWithFlags(&eS, cudaEventDisableTiming);
        cudaEventCreateWithFlags(&eG, cudaEventDisableTiming);
        inited = true;
    }

    float* p_h1t = symf(g_h1t);
    float* p_h2  = symf(g_h2);
    float* p_C   = symf(g_Cbig);
    float* p_O0  = symf(g_O0T);
    float* p_O1  = symf(g_O1T);
    float* p_O2  = symf(g_O2T);
    double* p_part = symd(g_part);
    float* p_s1 = symf(g_s1), *p_sh1 = symf(g_sh1);
    float* p_s2 = symf(g_s2), *p_sh2 = symf(g_sh2);
    float* p_sc0 = symf(g_sc0), *p_sf0 = symf(g_sf0);
    float* p_sc1 = symf(g_sc1), *p_sf1 = symf(g_sf1);
    float* p_sc2 = symf(g_sc2), *p_sf2 = symf(g_sf2);
    ush *aggh = symu(g_aggc_h), *aggl = symu(g_aggc_l);
    ush *w1h = symu(g_w1c_h), *w1l = symu(g_w1c_l);
    ush *h1h = symu(g_h1c_h), *h1l = symu(g_h1c_l);
    ush *w2h = symu(g_w2c_h), *w2l = symu(g_w2c_l);
    ush *Sh = symu(g_Sc_h), *Sl = symu(g_Sc_l);
    ush *Bmh = symu(g_BmTc_h), *Bml = symu(g_BmTc_l);
    ush *w0h = symu(g_c0wc_h), *w0l = symu(g_c0wc_l);
    ush *c1h = symu(g_c1wc_h), *c1l = symu(g_c1wc_l);
    ush *c2h = symu(g_c2wc_h), *c2l = symu(g_c2wc_l);

    // fork: side chain (ball -> BmT build -> conv-weight splits) on s1
    cudaEventRecord(eA, 0);
    cudaStreamWaitEvent(s1, eA, 0);
    sa_ball<<<(BQ*NQ*32)/256, 256, 0, s1>>>(xyz);
    sa_bmt_c<<<dim3(NQ/512, JQ, BQ), 256, 0, s1>>>(points, xyz);
    cv_split<<<(C0Q*KPE/2 + 255)/256, 256, 0, s1>>>(c0w, w0h, w0l, (long long)C0Q*KPE/2, INCH, KPE, nullptr, nullptr, 0);
    cv_split<<<(C1Q*C0Q/2 + 255)/256, 256, 0, s1>>>(c1w, c1h, c1l, (long long)C1Q*C0Q/2, C0Q, C0Q, nullptr, nullptr, 0);
    cv_split<<<(C2Q*C1Q/2 + 255)/256, 256, 0, s1>>>(c2w, c2h, c2l, (long long)C2Q*C1Q/2, C1Q, C1Q, nullptr, nullptr, 0);
    cudaEventRecord(eB, s1);

    // main chain
    sa_init<<<9, 256>>>();
    cv_agg<<<(int)(((long long)BQ*NQ*KP1/2 + 255)/256), 256>>>(points, xyz);
    cv_split<<<(SCQ*KP1/2 + 255)/256, 256>>>(w1_w, w1h, w1l, (long long)SCQ*KP1/2, SCQ, KP1, nullptr, nullptr, 0);
    cv_split<<<(SQ*KP1/2 + 255)/256, 256>>>(w2_w, w2h, w2l, (long long)SQ*KP1/2, SCQ, KP1, nullptr, nullptr, 0);

    // h1t = aggT * w1^T + w1_b ; col-stats fused
    mma_gemm<<<dim3(1, NQ/128, BQ), 256, SMEM_BYTES>>>(aggh, aggl, w1h, w1l, p_h1t,
        NQ, SCQ, KP1, (size_t)NQ*KP1, 0, (size_t)NQ*SCQ, nullptr, w1_b, 1, p_part, SCQ, 0, 0,
        0, nullptr, 0, nullptr, nullptr);
    sa_cs_fin<<<SCQ, 256>>>(SCQ, BQ*(NQ/128), BQ*NQ, bn1g, bn1b, p_s1, p_sh1);
    cv_split<<<(int)(((long long)BQ*NQ*KP1/2 + 255)/256), 256>>>(p_h1t, h1h, h1l,
        (long long)BQ*NQ*KP1/2, SCQ, KP1, p_s1, p_sh1, 0);

    // h2 = w2 * bn1(h1)^T + w2_b ; row-stats fused
    mma_gemm<<<dim3(NQ/128, SQ/128, BQ), 256, SMEM_BYTES>>>(w2h, w2l, h1h, h1l, p_h2,
        SQ, NQ, KP1, 0, (size_t)NQ*KP1, (size_t)SQ*NQ, w2_b, nullptr, 2, p_part, SQ, 0, 0,
        0, nullptr, 0, nullptr, nullptr);
    sa_cs_fin<<<SQ, 256>>>(SQ, BQ*(NQ/128), BQ*NQ, bn2g, bn2b, p_s2, p_sh2);
    sa_softmax<<<dim3(SQ, BQ), 256>>>(p_h2);
    cudaEventRecord(eS, 0);
    sa_flags<<<2, 256>>>();

    // Gram + cosine loss on s1 (overlaps Cbig/conv0 on main stream)
    cudaStreamWaitEvent(s1, eS, 0);
    mma_gemm<<<dim3(SQ/128, SQ/128, BQ), 256, SMEM_BYTES, s1>>>(Sh, Sl, Sh, Sl, p_h2,
        SQ, SQ, NQ, (size_t)SQ*NQ, (size_t)SQ*NQ, 0, nullptr, nullptr, 0, nullptr, 0, 1, 1,
        0, nullptr, 0, nullptr, nullptr);
    cudaEventRecord(eG, s1);

    // Cbig = S * BmT^T (needs BmT from side chain)
    cudaStreamWaitEvent(0, eB, 0);
    mma_gemm<<<dim3((JQ+127)/128, SQ/128, BQ), 256, SMEM_BYTES>>>(Sh, Sl, Bmh, Bml, p_C,
        SQ, JQ, NQ, (size_t)SQ*NQ, (size_t)JQ*NQ, (size_t)SQ*JQ, nullptr, nullptr, 0, nullptr, 0, 0, 0,
        0, nullptr, 0, nullptr, nullptr);
    sa_newxyz<<<(BQ*3*SQ + 255)/256, 256>>>(out);

    // conv0: A = edge features from Cbig in-loader (gather path)
    mma_gemm<<<dim3(1, KSQ/128, BQ), 256, SMEM_BYTES>>>(w0h, w0l, w0h, w0l, p_O0,
        KSQ, C0Q, KPE, 0, 0, (size_t)KSQ*C0Q, nullptr, c0b, 1, p_part, C0Q, 0, 0,
        2, p_C, (size_t)SQ*JQ, nullptr, nullptr);
    sa_cs_fin<<<C0Q, 256>>>(C0Q, BQ*(KSQ/128), BQ*KSQ, g0, b0, p_sc0, p_sf0);

    // conv1: A = bn-affine+leaky of O0 fp32, cp.async-staged (aMode=1)
    mma_gemm<<<dim3(1, KSQ/128, BQ), 256, SMEM_A1_BYTES>>>(c1h, c1l, c1h, c1l, p_O1,
        KSQ, C1Q, C0Q, 0, 0, (size_t)KSQ*C1Q, nullptr, c1b, 1, p_part, C1Q, 0, 0,
        1, p_O0, (size_t)KSQ*C0Q, p_sc0, p_sf0);
    sa_cs_fin<<<C1Q, 256>>>(C1Q, BQ*(KSQ/128), BQ*KSQ, g1, b1, p_sc1, p_sf1);

    // conv2: A = bn-affine+leaky of O1 fp32, cp.async-staged (aMode=1)
    mma_gemm<<<dim3(C2Q/128, KSQ/128, BQ), 256, SMEM_A1_BYTES>>>(c2h, c2l, c2h, c2l, p_O2,
        KSQ, C2Q, C1Q, 0, 0, (size_t)KSQ*C2Q, nullptr, c2b, 1, p_part, C2Q, 0, 0,
        1, p_O1, (size_t)KSQ*C1Q, p_sc1, p_sf1);
    sa_cs_fin<<<C2Q, 256>>>(C2Q, BQ*(KSQ/128), BQ*KSQ, g2, b2, p_sc2, p_sf2);

    sa_max<<<dim3(SQ, BQ), 256>>>(out);
    // join Gram branch before final scalars
    cudaStreamWaitEvent(0, eG, 0);
    sa_scalars<<<1, 256>>>(out);
}

// round 15
// speedup vs baseline: 1.0316x; 1.0316x over previous
#include <cuda_runtime.h>
#include <cuda_bf16.h>
#include <math.h>
#include <stdint.h>

#define BQ 16
#define NQ 2048
#define DQ 64
#define SQ 512
#define NSQ 32
#define SCQ 67
#define INCH 134
#define C0Q 128
#define C1Q 128
#define C2Q 256
#define KSQ (NSQ*SQ)
#define JQ (3+DQ+NSQ*DQ+NSQ*3)   // 2211
#define OFF_X 0
#define OFF_P 3
#define OFF_GP 67
#define OFF_GX 2115
#define XYZ_OUT (BQ*3*SQ)
#define NP_OUT  ((size_t)BQ*C2Q*SQ)
#define KP1 96
#define KPE 160

typedef unsigned short ush;

// ---------------- fp32 scratch ----------------
__device__ float g_h1t [(size_t)BQ*NQ*SCQ];
__device__ float g_h2  [(size_t)BQ*SQ*NQ];
__device__ float g_Cbig[(size_t)BQ*SQ*JQ];
__device__ float g_O0T [(size_t)BQ*KSQ*C0Q];
__device__ float g_O1T [(size_t)BQ*KSQ*C1Q];
__device__ float g_O2T [(size_t)BQ*KSQ*C2Q];
__device__ float g_norm[BQ*SQ];
__device__ int   g_amax[SQ];
__device__ int   g_idx[(size_t)BQ*NSQ*NQ];
__device__ double g_part[(size_t)2048*256*2];
__device__ float g_s1[SCQ], g_sh1[SCQ];
__device__ float g_s2[SQ],  g_sh2[SQ];
__device__ float g_sc0[C0Q], g_sf0[C0Q];
__device__ float g_sc1[C1Q], g_sf1[C1Q];
__device__ float g_sc2[C2Q], g_sf2[C2Q];
__device__ float g_acc[BQ];
__device__ int   g_flags[NQ];

// ---------------- bf16 hi/lo operand arrays ----------------
__device__ ush g_aggc_h[(size_t)BQ*NQ*KP1],  g_aggc_l[(size_t)BQ*NQ*KP1];
__device__ ush g_w1c_h[SCQ*KP1],             g_w1c_l[SCQ*KP1];
__device__ ush g_h1c_h[(size_t)BQ*NQ*KP1],   g_h1c_l[(size_t)BQ*NQ*KP1];
__device__ ush g_w2c_h[SQ*KP1],              g_w2c_l[SQ*KP1];
__device__ ush g_Sc_h[(size_t)BQ*SQ*NQ],     g_Sc_l[(size_t)BQ*SQ*NQ];
__device__ ush g_BmTc_h[(size_t)BQ*JQ*NQ],   g_BmTc_l[(size_t)BQ*JQ*NQ];
__device__ ush g_c0wc_h[C0Q*KPE],            g_c0wc_l[C0Q*KPE];
__device__ ush g_c1wc_h[C1Q*C0Q],            g_c1wc_l[C1Q*C0Q];
__device__ ush g_c2wc_h[C2Q*C1Q],            g_c2wc_l[C2Q*C1Q];

// ---------------- helpers ----------------
__device__ __forceinline__ uint32_t smem_u32(const void* p) {
    uint32_t a;
    asm("{ .reg .u64 t; cvta.to.shared.u64 t, %1; cvt.u32.u64 %0, t; }" : "=r"(a) : "l"(p));
    return a;
}
__device__ __forceinline__ void ldm4(uint32_t* r, uint32_t addr) {
    asm volatile("ldmatrix.sync.aligned.m8n8.x4.shared.b16 {%0,%1,%2,%3}, [%4];"
        : "=r"(r[0]), "=r"(r[1]), "=r"(r[2]), "=r"(r[3]) : "r"(addr));
}
__device__ __forceinline__ void mma16816(float* c, const uint32_t* a, const uint32_t* b) {
    asm volatile("mma.sync.aligned.m16n8k16.row.col.f32.bf16.bf16.f32 "
        "{%0,%1,%2,%3}, {%4,%5,%6,%7}, {%8,%9}, {%0,%1,%2,%3};"
        : "+f"(c[0]), "+f"(c[1]), "+f"(c[2]), "+f"(c[3])
        : "r"(a[0]), "r"(a[1]), "r"(a[2]), "r"(a[3]), "r"(b[0]), "r"(b[1]));
}
__device__ __forceinline__ uint32_t split_pack(float v0, float v1, uint32_t* lo) {
    __nv_bfloat16 h0 = __float2bfloat16(v0), h1 = __float2bfloat16(v1);
    __nv_bfloat16 l0 = __float2bfloat16(v0 - __bfloat162float(h0));
    __nv_bfloat16 l1 = __float2bfloat16(v1 - __bfloat162float(h1));
    *lo = ((uint32_t)__bfloat16_as_ushort(l1) << 16) | __bfloat16_as_ushort(l0);
    return ((uint32_t)__bfloat16_as_ushort(h1) << 16) | __bfloat16_as_ushort(h0);
}
__device__ __forceinline__ void split_write(float v, ush* ph, ush* pl) {
    __nv_bfloat16 h = __float2bfloat16(v);
    __nv_bfloat16 l = __float2bfloat16(v - __bfloat162float(h));
    *ph = __bfloat16_as_ushort(h);
    *pl = __bfloat16_as_ushort(l);
}
__device__ __forceinline__ float edge_val(const float* __restrict__ Cr, int k, int c) {
    if (c < 64) return Cr[OFF_P + c];
    if (c < 128) { int d = c - 64; return Cr[OFF_GP + k*DQ + d] - Cr[OFF_P + d]; }
    if (c < 131) return Cr[OFF_X + (c - 128)];
    if (c < INCH) { int c3 = c - 131; return Cr[OFF_GX + k*3 + c3] - Cr[OFF_X + c3]; }
    return 0.f;
}

// ---------------- pipelined HMMA GEMM (2-stage) with fused loaders/epilogues ----
#define KC 32
#define RSH 40
#define TILEH (128*RSH)
#define STAGEH (4*TILEH)
#define SMEM_BYTES (2*STAGEH*2)   // 81920 B
__global__ void __launch_bounds__(256, 2) mma_gemm(
    const ush* __restrict__ Ah, const ush* __restrict__ Al,
    const ush* __restrict__ Bh, const ush* __restrict__ Bl,
    float* __restrict__ C, int M, int N, int Kp,
    size_t sA, size_t sB, size_t sC,
    const float* __restrict__ biasRow, const float* __restrict__ biasCol,
    int statMode, double* __restrict__ statOut, int statC, int triSkip, int cosMode,
    int aMode, const float* __restrict__ Afp, size_t sAfp,
    const float* __restrict__ scA, const float* __restrict__ shA)
{
    if (triSkip && blockIdx.x < blockIdx.y) return;
    extern __shared__ ush sm[];
    const int tid = threadIdx.x;
    const int w = tid >> 5, lane = tid & 31;
    const int wm = w & 1, wn = w >> 1;
    const int m0 = blockIdx.y * 128, n0 = blockIdx.x * 128, b = blockIdx.z;
    const ush* srcs[4] = { Ah + (size_t)b*sA, Al + (size_t)b*sA,
                           Bh + (size_t)b*sB, Bl + (size_t)b*sB };
    const float* Afpb = Afp ? (Afp + (size_t)b * sAfp) : (const float*)0;
    const uint32_t smb = smem_u32(sm);

    float acc[4][4][4];
    #pragma unroll
    for (int i = 0; i < 4; i++)
        #pragma unroll
        for (int j = 0; j < 4; j++)
            #pragma unroll
            for (int q = 0; q < 4; q++) acc[i][j][q] = 0.f;

    const int T = Kp / KC;

    #define LOAD_STAGE(t, st) do { \
        int k0 = (t) * KC; \
        if (aMode == 0) { \
            _Pragma("unroll") \
            for (int arr = 0; arr < 2; arr++) { \
                const ush* S = srcs[arr]; \
                uint32_t dbase = smb + (uint32_t)(((st)*STAGEH + arr*TILEH) * 2); \
                _Pragma("unroll") \
                for (int i = 0; i < 2; i++) { \
                    int e = tid + i * 256; \
                    int r = e >> 2, c16 = e & 3; \
                    uint32_t daddr = dbase + (uint32_t)((r * RSH + c16 * 8) * 2); \
                    int rg = m0 + r; \
                    int rc = rg < M ? rg : (M - 1); \
                    const ush* sp = S + (size_t)rc * Kp + k0 + c16 * 8; \
                    int sz = (rg < M) ? 16 : 0; \
                    asm volatile("cp.async.cg.shared.global [%0], [%1], 16, %2;" \
                                 :: "r"(daddr), "l"(sp), "r"(sz)); \
                } \
            } \
        } else if (aMode == 1) { \
            _Pragma("unroll") \
            for (int i = 0; i < 8; i++) { \
                int e = tid + i * 256; \
                int r = e >> 4, cw = e & 15; \
                int rg = m0 + r, kk = k0 + cw * 2; \
                float v0 = 0.f, v1 = 0.f; \
                if (rg < M) { \
                    v0 = Afpb[(size_t)rg * Kp + kk]; \
                    v1 = Afpb[(size_t)rg * Kp + kk + 1]; \
                    v0 = scA[kk] * v0 + shA[kk];       if (v0 < 0.f) v0 *= 0.2f; \
                    v1 = scA[kk+1] * v1 + shA[kk+1];   if (v1 < 0.f) v1 *= 0.2f; \
                } \
                uint32_t lw, hw = split_pack(v0, v1, &lw); \
                int idx = (st)*STAGEH + r * RSH + cw * 2; \
                *(uint32_t*)&sm[idx] = hw; \
                *(uint32_t*)&sm[idx + TILEH] = lw; \
            } \
        } else { \
            _Pragma("unroll") \
            for (int i = 0; i < 8; i++) { \
                int e = tid + i * 256; \
                int r = e >> 4, cw = e & 15; \
                int rg = m0 + r, kk = k0 + cw * 2; \
                int kgrp = rg >> 9, sloc = rg & 511; \
                const float* Cr = Afpb + (size_t)sloc * JQ; \
                float v0 = edge_val(Cr, kgrp, kk); \
                float v1 = edge_val(Cr, kgrp, kk + 1); \
                uint32_t lw, hw = split_pack(v0, v1, &lw); \
                int idx = (st)*STAGEH + r * RSH + cw * 2; \
                *(uint32_t*)&sm[idx] = hw; \
                *(uint32_t*)&sm[idx + TILEH] = lw; \
            } \
        } \
        _Pragma("unroll") \
        for (int arr = 2; arr < 4; arr++) { \
            const ush* S = srcs[arr]; \
            uint32_t dbase = smb + (uint32_t)(((st)*STAGEH + arr*TILEH) * 2); \
            _Pragma("unroll") \
            for (int i = 0; i < 2; i++) { \
                int e = tid + i * 256; \
                int r = e >> 2, c16 = e & 3; \
                uint32_t daddr = dbase + (uint32_t)((r * RSH + c16 * 8) * 2); \
                int rg = n0 + r; \
                int rc = rg < N ? rg : (N - 1); \
                const ush* sp = S + (size_t)rc * Kp + k0 + c16 * 8; \
                int sz = (rg < N) ? 16 : 0; \
                asm volatile("cp.async.cg.shared.global [%0], [%1], 16, %2;" \
                             :: "r"(daddr), "l"(sp), "r"(sz)); \
            } \
        } \
        asm volatile("cp.async.commit_group;" ::: "memory"); \
    } while (0)

    LOAD_STAGE(0, 0);
    for (int t = 0; t < T; t++) {
        const int st = t & 1;
        if (t + 1 < T) {
            LOAD_STAGE(t + 1, st ^ 1);
            asm volatile("cp.async.wait_group 1;" ::: "memory");
        } else {
            asm volatile("cp.async.wait_group 0;" ::: "memory");
        }
        __syncthreads();
        const uint32_t uAh = smb + (uint32_t)((st*STAGEH + 0*TILEH) * 2);
        const uint32_t uAl = smb + (uint32_t)((st*STAGEH + 1*TILEH) * 2);
        const uint32_t uBh = smb + (uint32_t)((st*STAGEH + 2*TILEH) * 2);
        const uint32_t uBl = smb + (uint32_t)((st*STAGEH + 3*TILEH) * 2);
        #pragma unroll
        for (int k16 = 0; k16 < 32; k16 += 16) {
            const int arow = wm * 64 + (lane & 15);
            const int akk = k16 + ((lane >> 4) << 3);
            uint32_t bh[4][2], bl[4][2];
            {
                int q = lane >> 3;
                int brow0 = wn * 32 + ((q >> 1) << 3) + (lane & 7);
                int bkk = k16 + ((q & 1) << 3);
                #pragma unroll
                for (int p = 0; p < 2; p++) {
                    uint32_t byteoff = (uint32_t)(((brow0 + p * 16) * RSH + bkk) << 1);
                    uint32_t tmp[4];
                    ldm4(tmp, uBh + byteoff);
                    bh[2*p][0] = tmp[0]; bh[2*p][1] = tmp[1];
                    bh[2*p+1][0] = tmp[2]; bh[2*p+1][1] = tmp[3];
                    ldm4(tmp, uBl + byteoff);
                    bl[2*p][0] = tmp[0]; bl[2*p][1] = tmp[1];
                    bl[2*p+1][0] = tmp[2]; bl[2*p+1][1] = tmp[3];
                }
            }
            {
                // hi-A passes first: keeps ah live only through these two passes
                uint32_t ah[4][4];
                #pragma unroll
                for (int mf = 0; mf < 4; mf++) {
                    uint32_t byteoff = (uint32_t)(((arow + mf * 16) * RSH + akk) << 1);
                    ldm4(ah[mf], uAh + byteoff);
                }
                #pragma unroll
                for (int mf = 0; mf < 4; mf++)
                    #pragma unroll
                    for (int nf = 0; nf < 4; nf++)
                        mma16816(acc[mf][nf], ah[mf], bh[nf]);
                #pragma unroll
                for (int mf = 0; mf < 4; mf++)
                    #pragma unroll
                    for (int nf = 0; nf < 4; nf++)
                        mma16816(acc[mf][nf], ah[mf], bl[nf]);
            }
            {
                // lo-A pass last: al fragments allocated after ah is dead
                uint32_t al[4][4];
                #pragma unroll
                for (int mf = 0; mf < 4; mf++) {
                    uint32_t byteoff = (uint32_t)(((arow + mf * 16) * RSH + akk) << 1);
                    ldm4(al[mf], uAl + byteoff);
                }
                #pragma unroll
                for (int mf = 0; mf < 4; mf++)
                    #pragma unroll
                    for (int nf = 0; nf < 4; nf++)
                        mma16816(acc[mf][nf], al[mf], bh[nf]);
            }
        }
        __syncthreads();
    }

    if (cosMode) {
        const float* nb = g_norm + b * SQ;
        float part = 0.f;
        #pragma unroll
        for (int mf = 0; mf < 4; mf++) {
            int r = m0 + wm * 64 + mf * 16 + (lane >> 2);
            float nr0 = nb[r], nr1 = nb[r + 8];
            #pragma unroll
            for (int nf = 0; nf < 4; nf++) {
                #pragma unroll
                for (int u = 0; u < 2; u++) {
                    int col = n0 + wn * 32 + nf * 8 + ((lane & 3) << 1) + u;
                    float ncv = nb[col];
                    if (col > r) {
                        float cm = acc[mf][nf][u] / (nr0 * ncv + 1e-10f);
                        part += 2.f * cm * cm;
                    }
                    if (col > r + 8) {
                        float cm = acc[mf][nf][u + 2] / (nr1 * ncv + 1e-10f);
                        part += 2.f * cm * cm;
                    }
                }
            }
        }
        float* red = (float*)sm;
        red[tid] = part; __syncthreads();
        for (int off = 128; off > 0; off >>= 1) {
            if (tid < off) red[tid] += red[tid + off];
            __syncthreads();
        }
        if (tid == 0) atomicAdd(&g_acc[b], red[0]);
        return;
    }

    float cs[8], cq[8];
    #pragma unroll
    for (int i = 0; i < 8; i++) { cs[i] = 0.f; cq[i] = 0.f; }
    float* Cb = C + (size_t)b * sC;
    #pragma unroll
    for (int mf = 0; mf < 4; mf++) {
        int r = m0 + wm * 64 + mf * 16 + (lane >> 2);
        float br0 = biasRow ? biasRow[r] : 0.f;
        float br1 = biasRow ? biasRow[r + 8] : 0.f;
        #pragma unroll
        for (int nf = 0; nf < 4; nf++) {
            int c = n0 + wn * 32 + nf * 8 + ((lane & 3) << 1);
            #pragma unroll
            for (int u = 0; u < 2; u++) {
                int col = c + u;
                float bc = (biasCol && col < N) ? biasCol[col] : 0.f;
                float v0 = acc[mf][nf][u]     + br0 + bc;
                float v1 = acc[mf][nf][u + 2] + br1 + bc;
                if (col < N) {
                    Cb[(size_t)r * N + col]       = v0;
                    Cb[(size_t)(r + 8) * N + col] = v1;
                }
                if (statMode == 1) {
                    cs[nf*2+u] += v0 + v1;
                    cq[nf*2+u] += v0*v0 + v1*v1;
                } else if (statMode == 2) {
                    cs[mf*2]   += v0; cq[mf*2]   += v0*v0;
                    cs[mf*2+1] += v1; cq[mf*2+1] += v1*v1;
                }
            }
        }
    }
    if (statMode == 0) return;
    float* ssum = (float*)sm;
    float* ssq  = ssum + 2048;
    if (statMode == 1) {
        int g = wm * 8 + (lane >> 2);
        #pragma unroll
        for (int nf = 0; nf < 4; nf++)
            #pragma unroll
            for (int u = 0; u < 2; u++) {
                int colL = wn * 32 + nf * 8 + ((lane & 3) << 1) + u;
                ssum[colL * 16 + g] = cs[nf*2+u];
                ssq [colL * 16 + g] = cq[nf*2+u];
            }
        __syncthreads();
        if (tid < 128) {
            double s = 0.0, q = 0.0;
            #pragma unroll
            for (int g2 = 0; g2 < 16; g2++) { s += ssum[tid*16+g2]; q += ssq[tid*16+g2]; }
            int gcol = n0 + tid;
            if (gcol < N) {
                int chunk = blockIdx.z * gridDim.y + blockIdx.y;
                statOut[((size_t)chunk * statC + gcol) * 2]     = s;
                statOut[((size_t)chunk * statC + gcol) * 2 + 1] = q;
            }
        }
    } else {
        int h = wn * 4 + (lane & 3);
        #pragma unroll
        for (int mf = 0; mf < 4; mf++)
            #pragma unroll
            for (int hf = 0; hf < 2; hf++) {
                int rowL = wm * 64 + mf * 16 + (lane >> 2) + hf * 8;
                ssum[rowL * 16 + h] = cs[mf*2+hf];
                ssq [rowL * 16 + h] = cq[mf*2+hf];
            }
        __syncthreads();
        if (tid < 128) {
            double s = 0.0, q = 0.0;
            #pragma unroll
            for (int h2 = 0; h2 < 16; h2++) { s += ssum[tid*16+h2]; q += ssq[tid*16+h2]; }
            int grow = m0 + tid;
            int chunk = blockIdx.z * gridDim.x + blockIdx.x;
            statOut[((size_t)chunk * statC + grow) * 2]     = s;
            statOut[((size_t)chunk * statC + grow) * 2 + 1] = q;
        }
    }
}

// ---------------- elementwise / setup kernels ----------------
__global__ void sa_init() {
    int i = blockIdx.x * 256 + threadIdx.x;
    if (i < NQ) g_flags[i] = 0;
    if (i < BQ) g_acc[i] = 0.f;
}

__global__ void cv_split(const float* __restrict__ src, ush* __restrict__ dh, ush* __restrict__ dl,
                         long long totalPairs, int Ksrc, int Kp,
                         const float* __restrict__ sc, const float* __restrict__ sh, int leaky)
{
    long long i = (long long)blockIdx.x * 256 + threadIdx.x;
    if (i >= totalPairs) return;
    long long e = i * 2;
    int c = (int)(e % Kp);
    long long r = e / Kp;
    float v0 = 0.f, v1 = 0.f;
    if (c < Ksrc) {
        v0 = src[r * Ksrc + c];
        if (sc) { v0 = sc[c]*v0 + sh[c]; if (leaky && v0 < 0.f) v0 *= 0.2f; }
    }
    if (c + 1 < Ksrc) {
        v1 = src[r * Ksrc + c + 1];
        if (sc) { v1 = sc[c+1]*v1 + sh[c+1]; if (leaky && v1 < 0.f) v1 *= 0.2f; }
    }
    uint32_t lw, hw = split_pack(v0, v1, &lw);
    ((uint32_t*)dh)[i] = hw;
    ((uint32_t*)dl)[i] = lw;
}

__global__ void cv_agg(const float* __restrict__ points, const float* __restrict__ xyz) {
    long long i = (long long)blockIdx.x * 256 + threadIdx.x;
    if (i >= (long long)BQ*NQ*KP1/2) return;
    long long e = i * 2;
    int c = (int)(e % KP1); long long r = e / KP1;
    int n = (int)(r % NQ); int b = (int)(r / NQ);
    float v0 = 0.f, v1 = 0.f;
    if (c < DQ) v0 = points[((size_t)b*DQ + c)*NQ + n];
    else if (c < SCQ) v0 = xyz[((size_t)b*3 + (c-DQ))*NQ + n];
    int c1 = c + 1;
    if (c1 < DQ) v1 = points[((size_t)b*DQ + c1)*NQ + n];
    else if (c1 < SCQ) v1 = xyz[((size_t)b*3 + (c1-DQ))*NQ + n];
    uint32_t lw, hw = split_pack(v0, v1, &lw);
    ((uint32_t*)g_aggc_h)[i] = hw;
    ((uint32_t*)g_aggc_l)[i] = lw;
}

__global__ void sa_ball(const float* __restrict__ xyz) {
    int w = (blockIdx.x * blockDim.x + threadIdx.x) >> 5;
    int lane = threadIdx.x & 31;
    if (w >= BQ * NQ) return;
    int b = w / NQ, n = w % NQ;
    const float* X = xyz + (size_t)b * 3 * NQ;
    float px = X[n], py = X[NQ+n], pz = X[2*NQ+n];
    float pn = px*px + py*py + pz*pz;
    const float RR = (float)(0.2 * 0.2);
    int* out = g_idx + (size_t)b * NSQ * NQ + n;
    int cnt = 0;
    for (int j0 = 0; j0 < NQ && cnt < NSQ; j0 += 32) {
        int j = j0 + lane;
        float qx = X[j], qy = X[NQ+j], qz = X[2*NQ+j];
        float sq = (pn + qx*qx+qy*qy+qz*qz) - 2.0f*(px*qx+py*qy+pz*qz);
        bool in = !(sq > RR);
        unsigned m = __ballot_sync(0xffffffffu, in);
        int pos = cnt + __popc(m & ((1u << lane) - 1u));
        if (in && pos < NSQ) out[(size_t)pos * NQ] = j;
        cnt += __popc(m);
    }
    __syncwarp();
    if (lane == 0) {
        int first = out[0];
        for (int t = cnt; t < NSQ; t++) out[(size_t)t * NQ] = first;
    }
}

__global__ void sa_bmt_c(const float* __restrict__ points, const float* __restrict__ xyz) {
    int n = (blockIdx.x * 256 + threadIdx.x) * 2;
    int j = blockIdx.y, b = blockIdx.z;
    float v0, v1;
    if (j < OFF_P) {
        const float* p = xyz + ((size_t)b*3 + j)*NQ;
        v0 = p[n]; v1 = p[n+1];
    } else if (j < OFF_GP) {
        const float* p = points + ((size_t)b*DQ + (j-OFF_P))*NQ;
        v0 = p[n]; v1 = p[n+1];
    } else if (j < OFF_GX) {
        int t = j - OFF_GP, k = t >> 6, d = t & 63;
        const int* ip = g_idx + ((size_t)b*NSQ + k)*NQ;
        const float* p = points + ((size_t)b*DQ + d)*NQ;
        v0 = p[ip[n]]; v1 = p[ip[n+1]];
    } else {
        int t = j - OFF_GX, k = t / 3, c = t % 3;
        const int* ip = g_idx + ((size_t)b*NSQ + k)*NQ;
        const float* p = xyz + ((size_t)b*3 + c)*NQ;
        v0 = p[ip[n]]; v1 = p[ip[n+1]];
    }
    size_t o = (((size_t)b*JQ + j)*NQ + n) >> 1;
    uint32_t lw, hw = split_pack(v0, v1, &lw);
    ((uint32_t*)g_BmTc_h)[o] = hw;
    ((uint32_t*)g_BmTc_l)[o] = lw;
}

__global__ void sa_cs_fin(int C, int nChunks, int count,
                          const float* __restrict__ gamma, const float* __restrict__ beta,
                          float* __restrict__ sc, float* __restrict__ sf) {
    int c = blockIdx.x, tid = threadIdx.x;
    double s = 0.0, s2 = 0.0;
    for (int i = tid; i < nChunks; i += 256) {
        s  += g_part[((size_t)i * C + c) * 2];
        s2 += g_part[((size_t)i * C + c) * 2 + 1];
    }
    __shared__ double sa[256], sb2[256];
    sa[tid] = s; sb2[tid] = s2; __syncthreads();
    for (int o = 128; o > 0; o >>= 1) {
        if (tid < o) { sa[tid] += sa[tid+o]; sb2[tid] += sb2[tid+o]; }
        __syncthreads();
    }
    if (tid == 0) {
        double n = (double)count, m = sa[0] / n;
        double var = sb2[0] / n - m * m; if (var < 0.0) var = 0.0;
        float scale = gamma[c] * rsqrtf((float)var + 1e-5f);
        sc[c] = scale; sf[c] = beta[c] - (float)m * scale;
    }
}

__global__ void sa_softmax(float* __restrict__ H) {
    int s = blockIdx.x, b = blockIdx.y, tid = threadIdx.x;
    float* row = H + ((size_t)b * SQ + s) * NQ;
    __shared__ float buf[NQ];
    __shared__ float red[256], rv[256];
    __shared__ int ri[256];
    float a = g_s2[s], sh = g_sh2[s];
    float lmax = -3.4e38f;
    for (int i = tid; i < NQ; i += 256) { float y = a*row[i]+sh; buf[i] = y; lmax = fmaxf(lmax, y); }
    red[tid] = lmax; __syncthreads();
    for (int o = 128; o > 0; o >>= 1) { if (tid < o) red[tid] = fmaxf(red[tid], red[tid+o]); __syncthreads(); }
    float gmax = red[0]; __syncthreads();
    float lsum = 0.f;
    for (int i = tid; i < NQ; i += 256) { float e = __expf(buf[i]-gmax); buf[i] = e; lsum += e; }
    red[tid] = lsum; __syncthreads();
    for (int o = 128; o > 0; o >>= 1) { if (tid < o) red[tid] += red[tid+o]; __syncthreads(); }
    float inv = 1.f / red[0]; __syncthreads();
    float lss = 0.f, bm = -1.f; int bi = 0;
    size_t rowoff = ((size_t)b * SQ + s) * NQ;
    for (int i = tid; i < NQ; i += 256) {
        float v = buf[i] * inv; lss += v*v;
        split_write(v, g_Sc_h + rowoff + i, g_Sc_l + rowoff + i);
        if (v > bm) { bm = v; bi = i; }
    }
    red[tid] = lss; rv[tid] = bm; ri[tid] = bi; __syncthreads();
    for (int o = 128; o > 0; o >>= 1) {
        if (tid < o) {
            red[tid] += red[tid+o];
            if (rv[tid+o] > rv[tid] || (rv[tid+o] == rv[tid] && ri[tid+o] < ri[tid])) { rv[tid] = rv[tid+o]; ri[tid] = ri[tid+o]; }
        }
        __syncthreads();
    }
    if (tid == 0) {
        g_norm[b*SQ+s] = sqrtf(red[0]);
        if (b == 0) g_amax[s] = ri[0];
    }
}

__global__ void sa_flags() { int s = blockIdx.x*256 + threadIdx.x; if (s < SQ) g_flags[g_amax[s]] = 1; }

__global__ void sa_newxyz(float* __restrict__ out) {
    int i = blockIdx.x * 256 + threadIdx.x;
    if (i >= BQ*3*SQ) return;
    int s = i % SQ, c = (i/SQ) % 3, b = i/(3*SQ);
    out[i] = g_Cbig[((size_t)b*SQ + s)*JQ + OFF_X + c];
}

__global__ void sa_max(float* __restrict__ out) {
    int s = blockIdx.x, b = blockIdx.y, o = threadIdx.x;
    float sc = g_sc2[o], sf = g_sf2[o];
    float m = -3.4e38f;
    const float* base = g_O2T + ((size_t)b*KSQ + s)*C2Q + o;
    #pragma unroll
    for (int k = 0; k < NSQ; k++) {
        float y = sc * base[(size_t)k*SQ*C2Q] + sf;
        y = (y >= 0.f) ? y : 0.2f * y;
        m = fmaxf(m, y);
    }
    out[XYZ_OUT + ((size_t)b*C2Q + o)*SQ + s] = m;
}

__global__ void sa_scalars(float* __restrict__ out) {
    __shared__ float sfr[256]; __shared__ int sir[256];
    int tid = threadIdx.x;
    int cnt = 0;
    for (int i = tid; i < NQ; i += 256) cnt += g_flags[i];
    float l = (tid < BQ) ? sqrtf(g_acc[tid]) : 0.f;
    sfr[tid] = l; sir[tid] = cnt; __syncthreads();
    for (int o = 128; o > 0; o >>= 1) {
        if (tid < o) { sfr[tid] += sfr[tid+o]; sir[tid] += sir[tid+o]; }
        __syncthreads();
    }
    if (tid == 0) {
        out[XYZ_OUT + NP_OUT] = sfr[0] / (float)BQ;
        out[XYZ_OUT + NP_OUT + 1] = (float)sir[0];
    }
}

// ---------------- launch ----------------
static inline float*  symf(const void* sym) { void* p = nullptr; cudaGetSymbolAddress(&p, sym); return (float*)p; }
static inline ush*    symu(const void* sym) { void* p = nullptr; cudaGetSymbolAddress(&p, sym); return (ush*)p; }
static inline double* symd(const void* sym) { void* p = nullptr; cudaGetSymbolAddress(&p, sym); return (double*)p; }

extern "C" void kernel_launch(void* const* d_in, const int* in_sizes, int n_in,
                              void* d_out, int out_size)
{
    const float* xyz   = (const float*)d_in[0];
    const float* points= (const float*)d_in[1];
    const float* w1_w = (const float*)d_in[2];
    const float* w1_b = (const float*)d_in[3];
    const float* bn1g = (const float*)d_in[4];
    const float* bn1b = (const float*)d_in[5];
    const float* w2_w = (const float*)d_in[6];
    const float* w2_b = (const float*)d_in[7];
    const float* bn2g = (const float*)d_in[8];
    const float* bn2b = (const float*)d_in[9];
    const float* c0w = (const float*)d_in[10];
    const float* c0b = (const float*)d_in[11];
    const float* g0  = (const float*)d_in[12];
    const float* b0  = (const float*)d_in[13];
    const float* c1w = (const float*)d_in[14];
    const float* c1b = (const float*)d_in[15];
    const float* g1  = (const float*)d_in[16];
    const float* b1  = (const float*)d_in[17];
    const float* c2w = (const float*)d_in[18];
    const float* c2b = (const float*)d_in[19];
    const float* g2  = (const float*)d_in[20];
    const float* b2  = (const float*)d_in[21];
    float* out = (float*)d_out;

    static bool inited = false;
    static cudaStream_t s1;
    static cudaEvent_t eA, eB, eS, eG;
    if (!inited) {
        cudaFuncSetAttribute(mma_gemm, cudaFuncAttributeMaxDynamicSharedMemorySize, SMEM_BYTES);
        cudaStreamCreateWithFlags(&s1, cudaStreamNonBlocking);
        cudaEventCreateWithFlags(&eA, cudaEventDisableTiming);
        cudaEventCreateWithFlags(&eB, cudaEventDisableTiming);
        cudaEventCreateWithFlags(&eS, cudaEventDisableTiming);
        cudaEventCreateWithFlags(&eG, cudaEventDisableTiming);
        inited = true;
    }

    float* p_h1t = symf(g_h1t);
    float* p_h2  = symf(g_h2);
    float* p_C   = symf(g_Cbig);
    float* p_O0  = symf(g_O0T);
    float* p_O1  = symf(g_O1T);
    float* p_O2  = symf(g_O2T);
    double* p_part = symd(g_part);
    float* p_s1 = symf(g_s1), *p_sh1 = symf(g_sh1);
    float* p_s2 = symf(g_s2), *p_sh2 = symf(g_sh2);
    float* p_sc0 = symf(g_sc0), *p_sf0 = symf(g_sf0);
    float* p_sc1 = symf(g_sc1), *p_sf1 = symf(g_sf1);
    float* p_sc2 = symf(g_sc2), *p_sf2 = symf(g_sf2);
    ush *aggh = symu(g_aggc_h), *aggl = symu(g_aggc_l);
    ush *w1h = symu(g_w1c_h), *w1l = symu(g_w1c_l);
    ush *h1h = symu(g_h1c_h), *h1l = symu(g_h1c_l);
    ush *w2h = symu(g_w2c_h), *w2l = symu(g_w2c_l);
    ush *Sh = symu(g_Sc_h), *Sl = symu(g_Sc_l);
    ush *Bmh = symu(g_BmTc_h), *Bml = symu(g_BmTc_l);
    ush *w0h = symu(g_c0wc_h), *w0l = symu(g_c0wc_l);
    ush *c1h = symu(g_c1wc_h), *c1l = symu(g_c1wc_l);
    ush *c2h = symu(g_c2wc_h), *c2l = symu(g_c2wc_l);

    // fork: side chain (ball -> BmT build -> conv-weight splits) on s1
    cudaEventRecord(eA, 0);
    cudaStreamWaitEvent(s1, eA, 0);
    sa_ball<<<(BQ*NQ*32)/256, 256, 0, s1>>>(xyz);
    sa_bmt_c<<<dim3(NQ/512, JQ, BQ), 256, 0, s1>>>(points, xyz);
    cv_split<<<(C0Q*KPE/2 + 255)/256, 256, 0, s1>>>(c0w, w0h, w0l, (long long)C0Q*KPE/2, INCH, KPE, nullptr, nullptr, 0);
    cv_split<<<(C1Q*C0Q/2 + 255)/256, 256, 0, s1>>>(c1w, c1h, c1l, (long long)C1Q*C0Q/2, C0Q, C0Q, nullptr, nullptr, 0);
    cv_split<<<(C2Q*C1Q/2 + 255)/256, 256, 0, s1>>>(c2w, c2h, c2l, (long long)C2Q*C1Q/2, C1Q, C1Q, nullptr, nullptr, 0);
    cudaEventRecord(eB, s1);

    // main chain
    sa_init<<<9, 256>>>();
    cv_agg<<<(int)(((long long)BQ*NQ*KP1/2 + 255)/256), 256>>>(points, xyz);
    cv_split<<<(SCQ*KP1/2 + 255)/256, 256>>>(w1_w, w1h, w1l, (long long)SCQ*KP1/2, SCQ, KP1, nullptr, nullptr, 0);
    cv_split<<<(SQ*KP1/2 + 255)/256, 256>>>(w2_w, w2h, w2l, (long long)SQ*KP1/2, SCQ, KP1, nullptr, nullptr, 0);

    // h1t = aggT * w1^T + w1_b ; col-stats fused
    mma_gemm<<<dim3(1, NQ/128, BQ), 256, SMEM_BYTES>>>(aggh, aggl, w1h, w1l, p_h1t,
        NQ, SCQ, KP1, (size_t)NQ*KP1, 0, (size_t)NQ*SCQ, nullptr, w1_b, 1, p_part, SCQ, 0, 0,
        0, nullptr, 0, nullptr, nullptr);
    sa_cs_fin<<<SCQ, 256>>>(SCQ, BQ*(NQ/128), BQ*NQ, bn1g, bn1b, p_s1, p_sh1);
    cv_split<<<(int)(((long long)BQ*NQ*KP1/2 + 255)/256), 256>>>(p_h1t, h1h, h1l,
        (long long)BQ*NQ*KP1/2, SCQ, KP1, p_s1, p_sh1, 0);

    // h2 = w2 * bn1(h1)^T + w2_b ; row-stats fused
    mma_gemm<<<dim3(NQ/128, SQ/128, BQ), 256, SMEM_BYTES>>>(w2h, w2l, h1h, h1l, p_h2,
        SQ, NQ, KP1, 0, (size_t)NQ*KP1, (size_t)SQ*NQ, w2_b, nullptr, 2, p_part, SQ, 0, 0,
        0, nullptr, 0, nullptr, nullptr);
    sa_cs_fin<<<SQ, 256>>>(SQ, BQ*(NQ/128), BQ*NQ, bn2g, bn2b, p_s2, p_sh2);
    sa_softmax<<<dim3(SQ, BQ), 256>>>(p_h2);
    cudaEventRecord(eS, 0);
    sa_flags<<<2, 256>>>();

    // Gram + cosine loss on s1 (overlaps Cbig/conv0 on main stream)
    cudaStreamWaitEvent(s1, eS, 0);
    mma_gemm<<<dim3(SQ/128, SQ/128, BQ), 256, SMEM_BYTES, s1>>>(Sh, Sl, Sh, Sl, p_h2,
        SQ, SQ, NQ, (size_t)SQ*NQ, (size_t)SQ*NQ, 0, nullptr, nullptr, 0, nullptr, 0, 1, 1,
        0, nullptr, 0, nullptr, nullptr);
    cudaEventRecord(eG, s1);

    // Cbig = S * BmT^T (needs BmT from side chain)
    cudaStreamWaitEvent(0, eB, 0);
    mma_gemm<<<dim3((JQ+127)/128, SQ/128, BQ), 256, SMEM_BYTES>>>(Sh, Sl, Bmh, Bml, p_C,
        SQ, JQ, NQ, (size_t)SQ*NQ, (size_t)JQ*NQ, (size_t)SQ*JQ, nullptr, nullptr, 0, nullptr, 0, 0, 0,
        0, nullptr, 0, nullptr, nullptr);
    sa_newxyz<<<(BQ*3*SQ + 255)/256, 256>>>(out);

    // conv0: A = edge features from Cbig in-loader
    mma_gemm<<<dim3(1, KSQ/128, BQ), 256, SMEM_BYTES>>>(w0h, w0l, w0h, w0l, p_O0,
        KSQ, C0Q, KPE, 0, 0, (size_t)KSQ*C0Q, nullptr, c0b, 1, p_part, C0Q, 0, 0,
        2, p_C, (size_t)SQ*JQ, nullptr, nullptr);
    sa_cs_fin<<<C0Q, 256>>>(C0Q, BQ*(KSQ/128), BQ*KSQ, g0, b0, p_sc0, p_sf0);

    // conv1: A = bn-affine+leaky of O0 fp32 in-loader
    mma_gemm<<<dim3(1, KSQ/128, BQ), 256, SMEM_BYTES>>>(c1h, c1l, c1h, c1l, p_O1,
        KSQ, C1Q, C0Q, 0, 0, (size_t)KSQ*C1Q, nullptr, c1b, 1, p_part, C1Q, 0, 0,
        1, p_O0, (size_t)KSQ*C0Q, p_sc0, p_sf0);
    sa_cs_fin<<<C1Q, 256>>>(C1Q, BQ*(KSQ/128), BQ*KSQ, g1, b1, p_sc1, p_sf1);

    // conv2: A = bn-affine+leaky of O1 fp32 in-loader
    mma_gemm<<<dim3(C2Q/128, KSQ/128, BQ), 256, SMEM_BYTES>>>(c2h, c2l, c2h, c2l, p_O2,
        KSQ, C2Q, C1Q, 0, 0, (size_t)KSQ*C2Q, nullptr, c2b, 1, p_part, C2Q, 0, 0,
        1, p_O1, (size_t)KSQ*C1Q, p_sc1, p_sf1);
    sa_cs_fin<<<C2Q, 256>>>(C2Q, BQ*(KSQ/128), BQ*KSQ, g2, b2, p_sc2, p_sf2);

    sa_max<<<dim3(SQ, BQ), 256>>>(out);
    // join Gram branch before final scalars
    cudaStreamWaitEvent(0, eG, 0);
    sa_scalars<<<1, 256>>>(out);
}

// round 16
// speedup vs baseline: 1.0410x; 1.0091x over previous
#include <cuda_runtime.h>
#include <cuda_bf16.h>
#include <math.h>
#include <stdint.h>

#define BQ 16
#define NQ 2048
#define DQ 64
#define SQ 512
#define NSQ 32
#define SCQ 67
#define INCH 134
#define C0Q 128
#define C1Q 128
#define C2Q 256
#define KSQ (NSQ*SQ)
#define JQ (3+DQ+NSQ*DQ+NSQ*3)   // 2211
#define OFF_X 0
#define OFF_P 3
#define OFF_GP 67
#define OFF_GX 2115
#define XYZ_OUT (BQ*3*SQ)
#define NP_OUT  ((size_t)BQ*C2Q*SQ)
#define KP1 96
#define KPE 160

typedef unsigned short ush;

// ---------------- fp32 scratch ----------------
__device__ float g_h1t [(size_t)BQ*NQ*SCQ];
__device__ float g_h2  [(size_t)BQ*SQ*NQ];
__device__ float g_Cbig[(size_t)BQ*SQ*JQ];
__device__ float g_O0T [(size_t)BQ*KSQ*C0Q];
__device__ float g_O1T [(size_t)BQ*KSQ*C1Q];
__device__ unsigned g_mx[(size_t)BQ*SQ*C2Q];
__device__ unsigned g_mn[(size_t)BQ*SQ*C2Q];
__device__ float g_norm[BQ*SQ];
__device__ int   g_amax[SQ];
__device__ int   g_idx[(size_t)BQ*NSQ*NQ];
__device__ double g_part[(size_t)2048*256*2];
__device__ float g_s1[SCQ], g_sh1[SCQ];
__device__ float g_s2[SQ],  g_sh2[SQ];
__device__ float g_sc0[C0Q], g_sf0[C0Q];
__device__ float g_sc1[C1Q], g_sf1[C1Q];
__device__ float g_sc2[C2Q], g_sf2[C2Q];
__device__ float g_acc[BQ];
__device__ int   g_flags[NQ];

// ---------------- bf16 hi/lo operand arrays ----------------
__device__ ush g_aggc_h[(size_t)BQ*NQ*KP1],  g_aggc_l[(size_t)BQ*NQ*KP1];
__device__ ush g_w1c_h[SCQ*KP1],             g_w1c_l[SCQ*KP1];
__device__ ush g_h1c_h[(size_t)BQ*NQ*KP1],   g_h1c_l[(size_t)BQ*NQ*KP1];
__device__ ush g_w2c_h[SQ*KP1],              g_w2c_l[SQ*KP1];
__device__ ush g_Sc_h[(size_t)BQ*SQ*NQ],     g_Sc_l[(size_t)BQ*SQ*NQ];
__device__ ush g_BmTc_h[(size_t)BQ*JQ*NQ],   g_BmTc_l[(size_t)BQ*JQ*NQ];
__device__ ush g_c0wc_h[C0Q*KPE],            g_c0wc_l[C0Q*KPE];
__device__ ush g_c1wc_h[C1Q*C0Q],            g_c1wc_l[C1Q*C0Q];
__device__ ush g_c2wc_h[C2Q*C1Q],            g_c2wc_l[C2Q*C1Q];

// ---------------- helpers ----------------
__device__ __forceinline__ uint32_t smem_u32(const void* p) {
    uint32_t a;
    asm("{ .reg .u64 t; cvta.to.shared.u64 t, %1; cvt.u32.u64 %0, t; }" : "=r"(a) : "l"(p));
    return a;
}
__device__ __forceinline__ void ldm4(uint32_t* r, uint32_t addr) {
    asm volatile("ldmatrix.sync.aligned.m8n8.x4.shared.b16 {%0,%1,%2,%3}, [%4];"
        : "=r"(r[0]), "=r"(r[1]), "=r"(r[2]), "=r"(r[3]) : "r"(addr));
}
__device__ __forceinline__ void mma16816(float* c, const uint32_t* a, const uint32_t* b) {
    asm volatile("mma.sync.aligned.m16n8k16.row.col.f32.bf16.bf16.f32 "
        "{%0,%1,%2,%3}, {%4,%5,%6,%7}, {%8,%9}, {%0,%1,%2,%3};"
        : "+f"(c[0]), "+f"(c[1]), "+f"(c[2]), "+f"(c[3])
        : "r"(a[0]), "r"(a[1]), "r"(a[2]), "r"(a[3]), "r"(b[0]), "r"(b[1]));
}
__device__ __forceinline__ uint32_t split_pack(float v0, float v1, uint32_t* lo) {
    __nv_bfloat16 h0 = __float2bfloat16(v0), h1 = __float2bfloat16(v1);
    __nv_bfloat16 l0 = __float2bfloat16(v0 - __bfloat162float(h0));
    __nv_bfloat16 l1 = __float2bfloat16(v1 - __bfloat162float(h1));
    *lo = ((uint32_t)__bfloat16_as_ushort(l1) << 16) | __bfloat16_as_ushort(l0);
    return ((uint32_t)__bfloat16_as_ushort(h1) << 16) | __bfloat16_as_ushort(h0);
}
__device__ __forceinline__ void split_write(float v, ush* ph, ush* pl) {
    __nv_bfloat16 h = __float2bfloat16(v);
    __nv_bfloat16 l = __float2bfloat16(v - __bfloat162float(h));
    *ph = __bfloat16_as_ushort(h);
    *pl = __bfloat16_as_ushort(l);
}
__device__ __forceinline__ float edge_val(const float* __restrict__ Cr, int k, int c) {
    if (c < 64) return Cr[OFF_P + c];
    if (c < 128) { int d = c - 64; return Cr[OFF_GP + k*DQ + d] - Cr[OFF_P + d]; }
    if (c < 131) return Cr[OFF_X + (c - 128)];
    if (c < INCH) { int c3 = c - 131; return Cr[OFF_GX + k*3 + c3] - Cr[OFF_X + c3]; }
    return 0.f;
}
// order-preserving float<->uint encoding (for max/min via unsigned atomics)
__device__ __forceinline__ unsigned enc_f(float f) {
    unsigned u = __float_as_uint(f);
    return (u & 0x80000000u) ? ~u : (u | 0x80000000u);
}
__device__ __forceinline__ float dec_f(unsigned u) {
    u = (u & 0x80000000u) ? (u & 0x7FFFFFFFu) : ~u;
    return __uint_as_float(u);
}

// ---------------- pipelined HMMA GEMM (2-stage) with fused loaders/epilogues ----
// aMode: 0 pre-split bf16 A (cp.async); 1 fp32 A + affine/leaky; 2 edge features from Cbig
//        (rows ordered s*32+k). maxMode: no C store; per-(s,col) max/min over k in tile.
#define KC 32
#define RSH 40
#define TILEH (128*RSH)
#define STAGEH (4*TILEH)
#define SMEM_BYTES (2*STAGEH*2)   // 81920 B
__global__ void __launch_bounds__(256, 2) mma_gemm(
    const ush* __restrict__ Ah, const ush* __restrict__ Al,
    const ush* __restrict__ Bh, const ush* __restrict__ Bl,
    float* __restrict__ C, int M, int N, int Kp,
    size_t sA, size_t sB, size_t sC,
    const float* __restrict__ biasRow, const float* __restrict__ biasCol,
    int statMode, double* __restrict__ statOut, int statC, int triSkip, int cosMode,
    int aMode, const float* __restrict__ Afp, size_t sAfp,
    const float* __restrict__ scA, const float* __restrict__ shA,
    int maxMode, unsigned* __restrict__ mxOut, unsigned* __restrict__ mnOut)
{
    if (triSkip && blockIdx.x < blockIdx.y) return;
    extern __shared__ ush sm[];
    const int tid = threadIdx.x;
    const int w = tid >> 5, lane = tid & 31;
    const int wm = w & 1, wn = w >> 1;
    const int m0 = blockIdx.y * 128, n0 = blockIdx.x * 128, b = blockIdx.z;
    const ush* srcs[4] = { Ah + (size_t)b*sA, Al + (size_t)b*sA,
                           Bh + (size_t)b*sB, Bl + (size_t)b*sB };
    const float* Afpb = Afp ? (Afp + (size_t)b * sAfp) : (const float*)0;
    const uint32_t smb = smem_u32(sm);

    float acc[4][4][4];
    #pragma unroll
    for (int i = 0; i < 4; i++)
        #pragma unroll
        for (int j = 0; j < 4; j++)
            #pragma unroll
            for (int q = 0; q < 4; q++) acc[i][j][q] = 0.f;

    const int T = Kp / KC;

    #define LOAD_STAGE(t, st) do { \
        int k0 = (t) * KC; \
        if (aMode == 0) { \
            _Pragma("unroll") \
            for (int arr = 0; arr < 2; arr++) { \
                const ush* S = srcs[arr]; \
                uint32_t dbase = smb + (uint32_t)(((st)*STAGEH + arr*TILEH) * 2); \
                _Pragma("unroll") \
                for (int i = 0; i < 2; i++) { \
                    int e = tid + i * 256; \
                    int r = e >> 2, c16 = e & 3; \
                    uint32_t daddr = dbase + (uint32_t)((r * RSH + c16 * 8) * 2); \
                    int rg = m0 + r; \
                    int rc = rg < M ? rg : (M - 1); \
                    const ush* sp = S + (size_t)rc * Kp + k0 + c16 * 8; \
                    int sz = (rg < M) ? 16 : 0; \
                    asm volatile("cp.async.cg.shared.global [%0], [%1], 16, %2;" \
                                 :: "r"(daddr), "l"(sp), "r"(sz)); \
                } \
            } \
        } else if (aMode == 1) { \
            _Pragma("unroll") \
            for (int i = 0; i < 8; i++) { \
                int e = tid + i * 256; \
                int r = e >> 4, cw = e & 15; \
                int rg = m0 + r, kk = k0 + cw * 2; \
                float v0 = 0.f, v1 = 0.f; \
                if (rg < M) { \
                    v0 = Afpb[(size_t)rg * Kp + kk]; \
                    v1 = Afpb[(size_t)rg * Kp + kk + 1]; \
                    v0 = scA[kk] * v0 + shA[kk];       if (v0 < 0.f) v0 *= 0.2f; \
                    v1 = scA[kk+1] * v1 + shA[kk+1];   if (v1 < 0.f) v1 *= 0.2f; \
                } \
                uint32_t lw, hw = split_pack(v0, v1, &lw); \
                int idx = (st)*STAGEH + r * RSH + cw * 2; \
                *(uint32_t*)&sm[idx] = hw; \
                *(uint32_t*)&sm[idx + TILEH] = lw; \
            } \
        } else { \
            _Pragma("unroll") \
            for (int i = 0; i < 8; i++) { \
                int e = tid + i * 256; \
                int r = e >> 4, cw = e & 15; \
                int rg = m0 + r, kk = k0 + cw * 2; \
                int kgrp = rg & 31, sloc = rg >> 5; \
                const float* Cr = Afpb + (size_t)sloc * JQ; \
                float v0 = edge_val(Cr, kgrp, kk); \
                float v1 = edge_val(Cr, kgrp, kk + 1); \
                uint32_t lw, hw = split_pack(v0, v1, &lw); \
                int idx = (st)*STAGEH + r * RSH + cw * 2; \
                *(uint32_t*)&sm[idx] = hw; \
                *(uint32_t*)&sm[idx + TILEH] = lw; \
            } \
        } \
        _Pragma("unroll") \
        for (int arr = 2; arr < 4; arr++) { \
            const ush* S = srcs[arr]; \
            uint32_t dbase = smb + (uint32_t)(((st)*STAGEH + arr*TILEH) * 2); \
            _Pragma("unroll") \
            for (int i = 0; i < 2; i++) { \
                int e = tid + i * 256; \
                int r = e >> 2, c16 = e & 3; \
                uint32_t daddr = dbase + (uint32_t)((r * RSH + c16 * 8) * 2); \
                int rg = n0 + r; \
                int rc = rg < N ? rg : (N - 1); \
                const ush* sp = S + (size_t)rc * Kp + k0 + c16 * 8; \
                int sz = (rg < N) ? 16 : 0; \
                asm volatile("cp.async.cg.shared.global [%0], [%1], 16, %2;" \
                             :: "r"(daddr), "l"(sp), "r"(sz)); \
            } \
        } \
        asm volatile("cp.async.commit_group;" ::: "memory"); \
    } while (0)

    LOAD_STAGE(0, 0);
    for (int t = 0; t < T; t++) {
        const int st = t & 1;
        if (t + 1 < T) {
            LOAD_STAGE(t + 1, st ^ 1);
            asm volatile("cp.async.wait_group 1;" ::: "memory");
        } else {
            asm volatile("cp.async.wait_group 0;" ::: "memory");
        }
        __syncthreads();
        const uint32_t uAh = smb + (uint32_t)((st*STAGEH + 0*TILEH) * 2);
        const uint32_t uAl = smb + (uint32_t)((st*STAGEH + 1*TILEH) * 2);
        const uint32_t uBh = smb + (uint32_t)((st*STAGEH + 2*TILEH) * 2);
        const uint32_t uBl = smb + (uint32_t)((st*STAGEH + 3*TILEH) * 2);
        #pragma unroll
        for (int k16 = 0; k16 < 32; k16 += 16) {
            const int arow = wm * 64 + (lane & 15);
            const int akk = k16 + ((lane >> 4) << 3);
            uint32_t bh[4][2], bl[4][2];
            {
                int q = lane >> 3;
                int brow0 = wn * 32 + ((q >> 1) << 3) + (lane & 7);
                int bkk = k16 + ((q & 1) << 3);
                #pragma unroll
                for (int p = 0; p < 2; p++) {
                    uint32_t byteoff = (uint32_t)(((brow0 + p * 16) * RSH + bkk) << 1);
                    uint32_t tmp[4];
                    ldm4(tmp, uBh + byteoff);
                    bh[2*p][0] = tmp[0]; bh[2*p][1] = tmp[1];
                    bh[2*p+1][0] = tmp[2]; bh[2*p+1][1] = tmp[3];
                    ldm4(tmp, uBl + byteoff);
                    bl[2*p][0] = tmp[0]; bl[2*p][1] = tmp[1];
                    bl[2*p+1][0] = tmp[2]; bl[2*p+1][1] = tmp[3];
                }
            }
            {
                uint32_t ah[4][4];
                #pragma unroll
                for (int mf = 0; mf < 4; mf++) {
                    uint32_t byteoff = (uint32_t)(((arow + mf * 16) * RSH + akk) << 1);
                    ldm4(ah[mf], uAh + byteoff);
                }
                #pragma unroll
                for (int mf = 0; mf < 4; mf++)
                    #pragma unroll
                    for (int nf = 0; nf < 4; nf++)
                        mma16816(acc[mf][nf], ah[mf], bh[nf]);
                #pragma unroll
                for (int mf = 0; mf < 4; mf++)
                    #pragma unroll
                    for (int nf = 0; nf < 4; nf++)
                        mma16816(acc[mf][nf], ah[mf], bl[nf]);
            }
            {
                uint32_t al[4][4];
                #pragma unroll
                for (int mf = 0; mf < 4; mf++) {
                    uint32_t byteoff = (uint32_t)(((arow + mf * 16) * RSH + akk) << 1);
                    ldm4(al[mf], uAl + byteoff);
                }
                #pragma unroll
                for (int mf = 0; mf < 4; mf++)
                    #pragma unroll
                    for (int nf = 0; nf < 4; nf++)
                        mma16816(acc[mf][nf], al[mf], bh[nf]);
            }
        }
        __syncthreads();
    }

    if (cosMode) {
        const float* nb = g_norm + b * SQ;
        float part = 0.f;
        #pragma unroll
        for (int mf = 0; mf < 4; mf++) {
            int r = m0 + wm * 64 + mf * 16 + (lane >> 2);
            float nr0 = nb[r], nr1 = nb[r + 8];
            #pragma unroll
            for (int nf = 0; nf < 4; nf++) {
                #pragma unroll
                for (int u = 0; u < 2; u++) {
                    int col = n0 + wn * 32 + nf * 8 + ((lane & 3) << 1) + u;
                    float ncv = nb[col];
                    if (col > r) {
                        float cm = acc[mf][nf][u] / (nr0 * ncv + 1e-10f);
                        part += 2.f * cm * cm;
                    }
                    if (col > r + 8) {
                        float cm = acc[mf][nf][u + 2] / (nr1 * ncv + 1e-10f);
                        part += 2.f * cm * cm;
                    }
                }
            }
        }
        float* red = (float*)sm;
        red[tid] = part; __syncthreads();
        for (int off = 128; off > 0; off >>= 1) {
            if (tid < off) red[tid] += red[tid + off];
            __syncthreads();
        }
        if (tid == 0) atomicAdd(&g_acc[b], red[0]);
        return;
    }

    // epilogue
    unsigned* smx = (unsigned*)sm + 4096;   // after 16KB stats region
    unsigned* smn = smx + 512;
    if (maxMode) {
        for (int i = tid; i < 512; i += 256) { smx[i] = 0u; smn[i] = 0xFFFFFFFFu; }
        __syncthreads();
    }
    float cs[8], cq[8];
    #pragma unroll
    for (int i = 0; i < 8; i++) { cs[i] = 0.f; cq[i] = 0.f; }
    float* Cb = C + (size_t)b * sC;
    #pragma unroll
    for (int mf = 0; mf < 4; mf++) {
        int rl = wm * 64 + mf * 16 + (lane >> 2);
        int r = m0 + rl;
        float br0 = biasRow ? biasRow[r] : 0.f;
        float br1 = biasRow ? biasRow[r + 8] : 0.f;
        #pragma unroll
        for (int nf = 0; nf < 4; nf++) {
            int cl = wn * 32 + nf * 8 + ((lane & 3) << 1);
            #pragma unroll
            for (int u = 0; u < 2; u++) {
                int colL = cl + u;
                int col = n0 + colL;
                float bc = (biasCol && col < N) ? biasCol[col] : 0.f;
                float v0 = acc[mf][nf][u]     + br0 + bc;
                float v1 = acc[mf][nf][u + 2] + br1 + bc;
                if (maxMode) {
                    unsigned e0 = enc_f(v0), e1 = enc_f(v1);
                    atomicMax(&smx[(rl >> 5) * 128 + colL], e0);
                    atomicMin(&smn[(rl >> 5) * 128 + colL], e0);
                    atomicMax(&smx[((rl + 8) >> 5) * 128 + colL], e1);
                    atomicMin(&smn[((rl + 8) >> 5) * 128 + colL], e1);
                } else if (col < N) {
                    Cb[(size_t)r * N + col]       = v0;
                    Cb[(size_t)(r + 8) * N + col] = v1;
                }
                if (statMode == 1) {
                    cs[nf*2+u] += v0 + v1;
                    cq[nf*2+u] += v0*v0 + v1*v1;
                } else if (statMode == 2) {
                    cs[mf*2]   += v0; cq[mf*2]   += v0*v0;
                    cs[mf*2+1] += v1; cq[mf*2+1] += v1*v1;
                }
            }
        }
    }
    if (statMode == 0) return;
    float* ssum = (float*)sm;
    float* ssq  = ssum + 2048;
    if (statMode == 1) {
        int g = wm * 8 + (lane >> 2);
        #pragma unroll
        for (int nf = 0; nf < 4; nf++)
            #pragma unroll
            for (int u = 0; u < 2; u++) {
                int colL = wn * 32 + nf * 8 + ((lane & 3) << 1) + u;
                ssum[colL * 16 + g] = cs[nf*2+u];
                ssq [colL * 16 + g] = cq[nf*2+u];
            }
        __syncthreads();
        if (tid < 128) {
            double s = 0.0, q = 0.0;
            #pragma unroll
            for (int g2 = 0; g2 < 16; g2++) { s += ssum[tid*16+g2]; q += ssq[tid*16+g2]; }
            int gcol = n0 + tid;
            if (gcol < N) {
                int chunk = blockIdx.z * gridDim.y + blockIdx.y;
                statOut[((size_t)chunk * statC + gcol) * 2]     = s;
                statOut[((size_t)chunk * statC + gcol) * 2 + 1] = q;
            }
        }
    } else {
        int h = wn * 4 + (lane & 3);
        #pragma unroll
        for (int mf = 0; mf < 4; mf++)
            #pragma unroll
            for (int hf = 0; hf < 2; hf++) {
                int rowL = wm * 64 + mf * 16 + (lane >> 2) + hf * 8;
                ssum[rowL * 16 + h] = cs[mf*2+hf];
                ssq [rowL * 16 + h] = cq[mf*2+hf];
            }
        __syncthreads();
        if (tid < 128) {
            double s = 0.0, q = 0.0;
            #pragma unroll
            for (int h2 = 0; h2 < 16; h2++) { s += ssum[tid*16+h2]; q += ssq[tid*16+h2]; }
            int grow = m0 + tid;
            int chunk = blockIdx.z * gridDim.x + blockIdx.x;
            statOut[((size_t)chunk * statC + grow) * 2]     = s;
            statOut[((size_t)chunk * statC + grow) * 2 + 1] = q;
        }
    }
    if (maxMode) {
        int nS = M >> 5;   // total s rows
        for (int e = tid; e < 512; e += 256) {
            int sl = e >> 7, colL = e & 127;
            int sg = (m0 >> 5) + sl;
            int colg = n0 + colL;
            size_t oidx = ((size_t)b * nS + sg) * (size_t)N + colg;
            mxOut[oidx] = smx[e];
            mnOut[oidx] = smn[e];
        }
    }
}

// ---------------- elementwise / setup kernels ----------------
__global__ void sa_init() {
    int i = blockIdx.x * 256 + threadIdx.x;
    if (i < NQ) g_flags[i] = 0;
    if (i < BQ) g_acc[i] = 0.f;
}

__global__ void cv_split(const float* __restrict__ src, ush* __restrict__ dh, ush* __restrict__ dl,
                         long long totalPairs, int Ksrc, int Kp,
                         const float* __restrict__ sc, const float* __restrict__ sh, int leaky)
{
    long long i = (long long)blockIdx.x * 256 + threadIdx.x;
    if (i >= totalPairs) return;
    long long e = i * 2;
    int c = (int)(e % Kp);
    long long r = e / Kp;
    float v0 = 0.f, v1 = 0.f;
    if (c < Ksrc) {
        v0 = src[r * Ksrc + c];
        if (sc) { v0 = sc[c]*v0 + sh[c]; if (leaky && v0 < 0.f) v0 *= 0.2f; }
    }
    if (c + 1 < Ksrc) {
        v1 = src[r * Ksrc + c + 1];
        if (sc) { v1 = sc[c+1]*v1 + sh[c+1]; if (leaky && v1 < 0.f) v1 *= 0.2f; }
    }
    uint32_t lw, hw = split_pack(v0, v1, &lw);
    ((uint32_t*)dh)[i] = hw;
    ((uint32_t*)dl)[i] = lw;
}

__global__ void cv_agg(const float* __restrict__ points, const float* __restrict__ xyz) {
    long long i = (long long)blockIdx.x * 256 + threadIdx.x;
    if (i >= (long long)BQ*NQ*KP1/2) return;
    long long e = i * 2;
    int c = (int)(e % KP1); long long r = e / KP1;
    int n = (int)(r % NQ); int b = (int)(r / NQ);
    float v0 = 0.f, v1 = 0.f;
    if (c < DQ) v0 = points[((size_t)b*DQ + c)*NQ + n];
    else if (c < SCQ) v0 = xyz[((size_t)b*3 + (c-DQ))*NQ + n];
    int c1 = c + 1;
    if (c1 < DQ) v1 = points[((size_t)b*DQ + c1)*NQ + n];
    else if (c1 < SCQ) v1 = xyz[((size_t)b*3 + (c1-DQ))*NQ + n];
    uint32_t lw, hw = split_pack(v0, v1, &lw);
    ((uint32_t*)g_aggc_h)[i] = hw;
    ((uint32_t*)g_aggc_l)[i] = lw;
}

__global__ void sa_ball(const float* __restrict__ xyz) {
    int w = (blockIdx.x * blockDim.x + threadIdx.x) >> 5;
    int lane = threadIdx.x & 31;
    if (w >= BQ * NQ) return;
    int b = w / NQ, n = w % NQ;
    const float* X = xyz + (size_t)b * 3 * NQ;
    float px = X[n], py = X[NQ+n], pz = X[2*NQ+n];
    float pn = px*px + py*py + pz*pz;
    const float RR = (float)(0.2 * 0.2);
    int* out = g_idx + (size_t)b * NSQ * NQ + n;
    int cnt = 0;
    for (int j0 = 0; j0 < NQ && cnt < NSQ; j0 += 32) {
        int j = j0 + lane;
        float qx = X[j], qy = X[NQ+j], qz = X[2*NQ+j];
        float sq = (pn + qx*qx+qy*qy+qz*qz) - 2.0f*(px*qx+py*qy+pz*qz);
        bool in = !(sq > RR);
        unsigned m = __ballot_sync(0xffffffffu, in);
        int pos = cnt + __popc(m & ((1u << lane) - 1u));
        if (in && pos < NSQ) out[(size_t)pos * NQ] = j;
        cnt += __popc(m);
    }
    __syncwarp();
    if (lane == 0) {
        int first = out[0];
        for (int t = cnt; t < NSQ; t++) out[(size_t)t * NQ] = first;
    }
}

__global__ void sa_bmt_c(const float* __restrict__ points, const float* __restrict__ xyz) {
    int n = (blockIdx.x * 256 + threadIdx.x) * 2;
    int j = blockIdx.y, b = blockIdx.z;
    float v0, v1;
    if (j < OFF_P) {
        const float* p = xyz + ((size_t)b*3 + j)*NQ;
        v0 = p[n]; v1 = p[n+1];
    } else if (j < OFF_GP) {
        const float* p = points + ((size_t)b*DQ + (j-OFF_P))*NQ;
        v0 = p[n]; v1 = p[n+1];
    } else if (j < OFF_GX) {
        int t = j - OFF_GP, k = t >> 6, d = t & 63;
        const int* ip = g_idx + ((size_t)b*NSQ + k)*NQ;
        const float* p = points + ((size_t)b*DQ + d)*NQ;
        v0 = p[ip[n]]; v1 = p[ip[n+1]];
    } else {
        int t = j - OFF_GX, k = t / 3, c = t % 3;
        const int* ip = g_idx + ((size_t)b*NSQ + k)*NQ;
        const float* p = xyz + ((size_t)b*3 + c)*NQ;
        v0 = p[ip[n]]; v1 = p[ip[n+1]];
    }
    size_t o = (((size_t)b*JQ + j)*NQ + n) >> 1;
    uint32_t lw, hw = split_pack(v0, v1, &lw);
    ((uint32_t*)g_BmTc_h)[o] = hw;
    ((uint32_t*)g_BmTc_l)[o] = lw;
}

__global__ void sa_cs_fin(int C, int nChunks, int count,
                          const float* __restrict__ gamma, const float* __restrict__ beta,
                          float* __restrict__ sc, float* __restrict__ sf) {
    int c = blockIdx.x, tid = threadIdx.x;
    double s = 0.0, s2 = 0.0;
    for (int i = tid; i < nChunks; i += 256) {
        s  += g_part[((size_t)i * C + c) * 2];
        s2 += g_part[((size_t)i * C + c) * 2 + 1];
    }
    __shared__ double sa[256], sb2[256];
    sa[tid] = s; sb2[tid] = s2; __syncthreads();
    for (int o = 128; o > 0; o >>= 1) {
        if (tid < o) { sa[tid] += sa[tid+o]; sb2[tid] += sb2[tid+o]; }
        __syncthreads();
    }
    if (tid == 0) {
        double n = (double)count, m = sa[0] / n;
        double var = sb2[0] / n - m * m; if (var < 0.0) var = 0.0;
        float scale = gamma[c] * rsqrtf((float)var + 1e-5f);
        sc[c] = scale; sf[c] = beta[c] - (float)m * scale;
    }
}

__global__ void sa_softmax(float* __restrict__ H) {
    int s = blockIdx.x, b = blockIdx.y, tid = threadIdx.x;
    float* row = H + ((size_t)b * SQ + s) * NQ;
    __shared__ float buf[NQ];
    __shared__ float red[256], rv[256];
    __shared__ int ri[256];
    float a = g_s2[s], sh = g_sh2[s];
    float lmax = -3.4e38f;
    for (int i = tid; i < NQ; i += 256) { float y = a*row[i]+sh; buf[i] = y; lmax = fmaxf(lmax, y); }
    red[tid] = lmax; __syncthreads();
    for (int o = 128; o > 0; o >>= 1) { if (tid < o) red[tid] = fmaxf(red[tid], red[tid+o]); __syncthreads(); }
    float gmax = red[0]; __syncthreads();
    float lsum = 0.f;
    for (int i = tid; i < NQ; i += 256) { float e = __expf(buf[i]-gmax); buf[i] = e; lsum += e; }
    red[tid] = lsum; __syncthreads();
    for (int o = 128; o > 0; o >>= 1) { if (tid < o) red[tid] += red[tid+o]; __syncthreads(); }
    float inv = 1.f / red[0]; __syncthreads();
    float lss = 0.f, bm = -1.f; int bi = 0;
    size_t rowoff = ((size_t)b * SQ + s) * NQ;
    for (int i = tid; i < NQ; i += 256) {
        float v = buf[i] * inv; lss += v*v;
        split_write(v, g_Sc_h + rowoff + i, g_Sc_l + rowoff + i);
        if (v > bm) { bm = v; bi = i; }
    }
    red[tid] = lss; rv[tid] = bm; ri[tid] = bi; __syncthreads();
    for (int o = 128; o > 0; o >>= 1) {
        if (tid < o) {
            red[tid] += red[tid+o];
            if (rv[tid+o] > rv[tid] || (rv[tid+o] == rv[tid] && ri[tid+o] < ri[tid])) { rv[tid] = rv[tid+o]; ri[tid] = ri[tid+o]; }
        }
        __syncthreads();
    }
    if (tid == 0) {
        g_norm[b*SQ+s] = sqrtf(red[0]);
        if (b == 0) g_amax[s] = ri[0];
    }
}

__global__ void sa_flags() { int s = blockIdx.x*256 + threadIdx.x; if (s < SQ) g_flags[g_amax[s]] = 1; }

__global__ void sa_newxyz(float* __restrict__ out) {
    int i = blockIdx.x * 256 + threadIdx.x;
    if (i >= BQ*3*SQ) return;
    int s = i % SQ, c = (i/SQ) % 3, b = i/(3*SQ);
    out[i] = g_Cbig[((size_t)b*SQ + s)*JQ + OFF_X + c];
}

// final: bn2 affine + leaky on k-maxed (or k-minned if scale<0) conv2 outputs
__global__ void sa_max(float* __restrict__ out,
                       const unsigned* __restrict__ mx, const unsigned* __restrict__ mn) {
    int s = blockIdx.x, b = blockIdx.y, o = threadIdx.x;
    size_t idx = ((size_t)b * SQ + s) * C2Q + o;
    float sc = g_sc2[o], sf = g_sf2[o];
    float v = (sc >= 0.f) ? dec_f(mx[idx]) : dec_f(mn[idx]);
    float y = sc * v + sf;
    y = (y >= 0.f) ? y : 0.2f * y;
    out[XYZ_OUT + ((size_t)b*C2Q + o)*SQ + s] = y;
}

__global__ void sa_scalars(float* __restrict__ out) {
    __shared__ float sfr[256]; __shared__ int sir[256];
    int tid = threadIdx.x;
    int cnt = 0;
    for (int i = tid; i < NQ; i += 256) cnt += g_flags[i];
    float l = (tid < BQ) ? sqrtf(g_acc[tid]) : 0.f;
    sfr[tid] = l; sir[tid] = cnt; __syncthreads();
    for (int o = 128; o > 0; o >>= 1) {
        if (tid < o) { sfr[tid] += sfr[tid+o]; sir[tid] += sir[tid+o]; }
        __syncthreads();
    }
    if (tid == 0) {
        out[XYZ_OUT + NP_OUT] = sfr[0] / (float)BQ;
        out[XYZ_OUT + NP_OUT + 1] = (float)sir[0];
    }
}

// ---------------- launch ----------------
static inline float*    symf(const void* sym) { void* p = nullptr; cudaGetSymbolAddress(&p, sym); return (float*)p; }
static inline ush*      symu(const void* sym) { void* p = nullptr; cudaGetSymbolAddress(&p, sym); return (ush*)p; }
static inline double*   symd(const void* sym) { void* p = nullptr; cudaGetSymbolAddress(&p, sym); return (double*)p; }
static inline unsigned* symx(const void* sym) { void* p = nullptr; cudaGetSymbolAddress(&p, sym); return (unsigned*)p; }

extern "C" void kernel_launch(void* const* d_in, const int* in_sizes, int n_in,
                              void* d_out, int out_size)
{
    const float* xyz   = (const float*)d_in[0];
    const float* points= (const float*)d_in[1];
    const float* w1_w = (const float*)d_in[2];
    const float* w1_b = (const float*)d_in[3];
    const float* bn1g = (const float*)d_in[4];
    const float* bn1b = (const float*)d_in[5];
    const float* w2_w = (const float*)d_in[6];
    const float* w2_b = (const float*)d_in[7];
    const float* bn2g = (const float*)d_in[8];
    const float* bn2b = (const float*)d_in[9];
    const float* c0w = (const float*)d_in[10];
    const float* c0b = (const float*)d_in[11];
    const float* g0  = (const float*)d_in[12];
    const float* b0  = (const float*)d_in[13];
    const float* c1w = (const float*)d_in[14];
    const float* c1b = (const float*)d_in[15];
    const float* g1  = (const float*)d_in[16];
    const float* b1  = (const float*)d_in[17];
    const float* c2w = (const float*)d_in[18];
    const float* c2b = (const float*)d_in[19];
    const float* g2  = (const float*)d_in[20];
    const float* b2  = (const float*)d_in[21];
    float* out = (float*)d_out;

    static bool inited = false;
    static cudaStream_t s1;
    static cudaEvent_t eA, eB, eS, eG;
    if (!inited) {
        cudaFuncSetAttribute(mma_gemm, cudaFuncAttributeMaxDynamicSharedMemorySize, SMEM_BYTES);
        cudaStreamCreateWithFlags(&s1, cudaStreamNonBlocking);
        cudaEventCreateWithFlags(&eA, cudaEventDisableTiming);
        cudaEventCreateWithFlags(&eB, cudaEventDisableTiming);
        cudaEventCreateWithFlags(&eS, cudaEventDisableTiming);
        cudaEventCreateWithFlags(&eG, cudaEventDisableTiming);
        inited = true;
    }

    float* p_h1t = symf(g_h1t);
    float* p_h2  = symf(g_h2);
    float* p_C   = symf(g_Cbig);
    float* p_O0  = symf(g_O0T);
    float* p_O1  = symf(g_O1T);
    unsigned* p_mx = symx(g_mx);
    unsigned* p_mn = symx(g_mn);
    double* p_part = symd(g_part);
    float* p_s1 = symf(g_s1), *p_sh1 = symf(g_sh1);
    float* p_s2 = symf(g_s2), *p_sh2 = symf(g_sh2);
    float* p_sc0 = symf(g_sc0), *p_sf0 = symf(g_sf0);
    float* p_sc1 = symf(g_sc1), *p_sf1 = symf(g_sf1);
    float* p_sc2 = symf(g_sc2), *p_sf2 = symf(g_sf2);
    ush *aggh = symu(g_aggc_h), *aggl = symu(g_aggc_l);
    ush *w1h = symu(g_w1c_h), *w1l = symu(g_w1c_l);
    ush *h1h = symu(g_h1c_h), *h1l = symu(g_h1c_l);
    ush *w2h = symu(g_w2c_h), *w2l = symu(g_w2c_l);
    ush *Sh = symu(g_Sc_h), *Sl = symu(g_Sc_l);
    ush *Bmh = symu(g_BmTc_h), *Bml = symu(g_BmTc_l);
    ush *w0h = symu(g_c0wc_h), *w0l = symu(g_c0wc_l);
    ush *c1h = symu(g_c1wc_h), *c1l = symu(g_c1wc_l);
    ush *c2h = symu(g_c2wc_h), *c2l = symu(g_c2wc_l);

    // fork: side chain (ball -> BmT build -> conv-weight splits) on s1
    cudaEventRecord(eA, 0);
    cudaStreamWaitEvent(s1, eA, 0);
    sa_ball<<<(BQ*NQ*32)/256, 256, 0, s1>>>(xyz);
    sa_bmt_c<<<dim3(NQ/512, JQ, BQ), 256, 0, s1>>>(points, xyz);
    cv_split<<<(C0Q*KPE/2 + 255)/256, 256, 0, s1>>>(c0w, w0h, w0l, (long long)C0Q*KPE/2, INCH, KPE, nullptr, nullptr, 0);
    cv_split<<<(C1Q*C0Q/2 + 255)/256, 256, 0, s1>>>(c1w, c1h, c1l, (long long)C1Q*C0Q/2, C0Q, C0Q, nullptr, nullptr, 0);
    cv_split<<<(C2Q*C1Q/2 + 255)/256, 256, 0, s1>>>(c2w, c2h, c2l, (long long)C2Q*C1Q/2, C1Q, C1Q, nullptr, nullptr, 0);
    cudaEventRecord(eB, s1);

    // main chain
    sa_init<<<9, 256>>>();
    cv_agg<<<(int)(((long long)BQ*NQ*KP1/2 + 255)/256), 256>>>(points, xyz);
    cv_split<<<(SCQ*KP1/2 + 255)/256, 256>>>(w1_w, w1h, w1l, (long long)SCQ*KP1/2, SCQ, KP1, nullptr, nullptr, 0);
    cv_split<<<(SQ*KP1/2 + 255)/256, 256>>>(w2_w, w2h, w2l, (long long)SQ*KP1/2, SCQ, KP1, nullptr, nullptr, 0);

    // h1t = aggT * w1^T + w1_b ; col-stats fused
    mma_gemm<<<dim3(1, NQ/128, BQ), 256, SMEM_BYTES>>>(aggh, aggl, w1h, w1l, p_h1t,
        NQ, SCQ, KP1, (size_t)NQ*KP1, 0, (size_t)NQ*SCQ, nullptr, w1_b, 1, p_part, SCQ, 0, 0,
        0, nullptr, 0, nullptr, nullptr, 0, nullptr, nullptr);
    sa_cs_fin<<<SCQ, 256>>>(SCQ, BQ*(NQ/128), BQ*NQ, bn1g, bn1b, p_s1, p_sh1);
    cv_split<<<(int)(((long long)BQ*NQ*KP1/2 + 255)/256), 256>>>(p_h1t, h1h, h1l,
        (long long)BQ*NQ*KP1/2, SCQ, KP1, p_s1, p_sh1, 0);

    // h2 = w2 * bn1(h1)^T + w2_b ; row-stats fused
    mma_gemm<<<dim3(NQ/128, SQ/128, BQ), 256, SMEM_BYTES>>>(w2h, w2l, h1h, h1l, p_h2,
        SQ, NQ, KP1, 0, (size_t)NQ*KP1, (size_t)SQ*NQ, w2_b, nullptr, 2, p_part, SQ, 0, 0,
        0, nullptr, 0, nullptr, nullptr, 0, nullptr, nullptr);
    sa_cs_fin<<<SQ, 256>>>(SQ, BQ*(NQ/128), BQ*NQ, bn2g, bn2b, p_s2, p_sh2);
    sa_softmax<<<dim3(SQ, BQ), 256>>>(p_h2);
    cudaEventRecord(eS, 0);
    sa_flags<<<2, 256>>>();

    // Gram + cosine loss on s1 (overlaps Cbig/conv0 on main stream)
    cudaStreamWaitEvent(s1, eS, 0);
    mma_gemm<<<dim3(SQ/128, SQ/128, BQ), 256, SMEM_BYTES, s1>>>(Sh, Sl, Sh, Sl, p_h2,
        SQ, SQ, NQ, (size_t)SQ*NQ, (size_t)SQ*NQ, 0, nullptr, nullptr, 0, nullptr, 0, 1, 1,
        0, nullptr, 0, nullptr, nullptr, 0, nullptr, nullptr);
    cudaEventRecord(eG, s1);

    // Cbig = S * BmT^T (needs BmT from side chain)
    cudaStreamWaitEvent(0, eB, 0);
    mma_gemm<<<dim3((JQ+127)/128, SQ/128, BQ), 256, SMEM_BYTES>>>(Sh, Sl, Bmh, Bml, p_C,
        SQ, JQ, NQ, (size_t)SQ*NQ, (size_t)JQ*NQ, (size_t)SQ*JQ, nullptr, nullptr, 0, nullptr, 0, 0, 0,
        0, nullptr, 0, nullptr, nullptr, 0, nullptr, nullptr);
    sa_newxyz<<<(BQ*3*SQ + 255)/256, 256>>>(out);

    // conv0: A = edge features from Cbig in-loader (rows s*32+k)
    mma_gemm<<<dim3(1, KSQ/128, BQ), 256, SMEM_BYTES>>>(w0h, w0l, w0h, w0l, p_O0,
        KSQ, C0Q, KPE, 0, 0, (size_t)KSQ*C0Q, nullptr, c0b, 1, p_part, C0Q, 0, 0,
        2, p_C, (size_t)SQ*JQ, nullptr, nullptr, 0, nullptr, nullptr);
    sa_cs_fin<<<C0Q, 256>>>(C0Q, BQ*(KSQ/128), BQ*KSQ, g0, b0, p_sc0, p_sf0);

    // conv1: A = bn-affine+leaky of O0 fp32 in-loader
    mma_gemm<<<dim3(1, KSQ/128, BQ), 256, SMEM_BYTES>>>(c1h, c1l, c1h, c1l, p_O1,
        KSQ, C1Q, C0Q, 0, 0, (size_t)KSQ*C1Q, nullptr, c1b, 1, p_part, C1Q, 0, 0,
        1, p_O0, (size_t)KSQ*C0Q, p_sc0, p_sf0, 0, nullptr, nullptr);
    sa_cs_fin<<<C1Q, 256>>>(C1Q, BQ*(KSQ/128), BQ*KSQ, g1, b1, p_sc1, p_sf1);

    // conv2: no C store; fused k-max/min + stats epilogue
    mma_gemm<<<dim3(C2Q/128, KSQ/128, BQ), 256, SMEM_BYTES>>>(c2h, c2l, c2h, c2l, p_h1t,
        KSQ, C2Q, C1Q, 0, 0, 0, nullptr, c2b, 1, p_part, C2Q, 0, 0,
        1, p_O1, (size_t)KSQ*C1Q, p_sc1, p_sf1, 1, p_mx, p_mn);
    sa_cs_fin<<<C2Q, 256>>>(C2Q, BQ*(KSQ/128), BQ*KSQ, g2, b2, p_sc2, p_sf2);

    sa_max<<<dim3(SQ, BQ), 256>>>(out, p_mx, p_mn);
    // join Gram branch before final scalars
    cudaStreamWaitEvent(0, eG, 0);
    sa_scalars<<<1, 256>>>(out);
}